// round 1
// baseline (speedup 1.0000x reference)
#include <cuda_runtime.h>
#include <math.h>

#define S_TOT 8192           // T*H*W = 8*32*32
#define CCH   512
#define NELEM (CCH * S_TOT)  // 4,194,304

// ---------------- scratch (device globals: allocation-free) ----------------
__device__ float g_buf0[NELEM];
__device__ float g_buf1[NELEM];
__device__ float g_buf2[NELEM];
__device__ float g_q[NELEM];
__device__ float g_k[NELEM];
__device__ float g_v[NELEM];
__device__ float g_scores[(size_t)S_TOT * S_TOT];  // 256 MB
__device__ float g_mean[32];
__device__ float g_rstd[32];

// ---------------- GroupNorm: stats (two-pass, 1 block per group) -----------
__global__ void gn_stats_kernel(const float* __restrict__ x) {
    __shared__ float red[512];
    int g = blockIdx.x;
    const float* base = x + (size_t)g * 16 * S_TOT;
    const int N = 16 * S_TOT;  // 131072
    float s = 0.f;
    for (int i = threadIdx.x; i < N; i += 512) s += base[i];
    red[threadIdx.x] = s;
    __syncthreads();
    for (int off = 256; off > 0; off >>= 1) {
        if (threadIdx.x < off) red[threadIdx.x] += red[threadIdx.x + off];
        __syncthreads();
    }
    float mean = red[0] * (1.f / (float)N);
    __syncthreads();
    float ss = 0.f;
    for (int i = threadIdx.x; i < N; i += 512) {
        float d = base[i] - mean;
        ss += d * d;
    }
    red[threadIdx.x] = ss;
    __syncthreads();
    for (int off = 256; off > 0; off >>= 1) {
        if (threadIdx.x < off) red[threadIdx.x] += red[threadIdx.x + off];
        __syncthreads();
    }
    if (threadIdx.x == 0) {
        g_mean[g] = mean;
        g_rstd[g] = rsqrtf(red[0] * (1.f / (float)N) + 1e-6f);
    }
}

// ---------------- GroupNorm apply (+optional SiLU), vectorized -------------
__global__ void gn_apply_kernel(const float* __restrict__ x, float* __restrict__ y,
                                const float* __restrict__ sc, const float* __restrict__ bi,
                                int do_silu) {
    int i4 = blockIdx.x * blockDim.x + threadIdx.x;  // float4 index
    int c = i4 >> 11;          // (i4*4)/8192
    int g = c >> 4;
    float rstd = g_rstd[g];
    float a = sc[c] * rstd;
    float b = bi[c] - g_mean[g] * a;
    float4 v = ((const float4*)x)[i4];
    float4 r;
    r.x = a * v.x + b;
    r.y = a * v.y + b;
    r.z = a * v.z + b;
    r.w = a * v.w + b;
    if (do_silu) {
        r.x = r.x / (1.f + expf(-r.x));
        r.y = r.y / (1.f + expf(-r.y));
        r.z = r.z / (1.f + expf(-r.z));
        r.w = r.w / (1.f + expf(-r.w));
    }
    ((float4*)y)[i4] = r;
}

// ---------------- Causal Conv3d (3x3x3, edge pad t:(2,0), h/w:(1,1)) -------
// Block: 256 threads = 8 h-rows x 32 w cols at one t; 64 output channels.
// Per input channel: smem <- 64x27 weights + 3x10x34 halo patch; 1728 FMA/thread.
__global__ void __launch_bounds__(256, 2)
conv3d_kernel(const float* __restrict__ in, const float* __restrict__ w,
              const float* __restrict__ bias, const float* __restrict__ resid,
              float* __restrict__ out) {
    __shared__ __align__(16) float ws[27][64];
    __shared__ float xs[3][10][34];
    int ot = blockIdx.x * 64;
    int t  = blockIdx.y;
    int h0 = blockIdx.z * 8;
    int tid = threadIdx.x;
    int lh = tid >> 5, lw = tid & 31;

    float acc[64];
#pragma unroll
    for (int o = 0; o < 64; o++) acc[o] = 0.f;

    for (int ci = 0; ci < 512; ci++) {
        __syncthreads();
        // weights: ws[tap][o] = w[(ot+o, ci, tap)]
        for (int idx = tid; idx < 27 * 64; idx += 256) {
            int o = idx / 27, tap = idx - o * 27;
            ws[tap][o] = w[((size_t)(ot + o) * 512 + ci) * 27 + tap];
        }
        // input halo patch with replicate clamping
        const float* inc = in + (size_t)ci * S_TOT;
        for (int idx = tid; idx < 1020; idx += 256) {
            int kd = idx / 340, r = idx - kd * 340;
            int hh = r / 34, ww = r - hh * 34;
            int ts = t - 2 + kd; if (ts < 0) ts = 0;
            int sh = h0 - 1 + hh; sh = sh < 0 ? 0 : (sh > 31 ? 31 : sh);
            int sw = ww - 1;      sw = sw < 0 ? 0 : (sw > 31 ? 31 : sw);
            xs[kd][hh][ww] = inc[ts * 1024 + sh * 32 + sw];
        }
        __syncthreads();
#pragma unroll
        for (int kd = 0; kd < 3; kd++)
#pragma unroll
            for (int kh = 0; kh < 3; kh++)
#pragma unroll
                for (int kw = 0; kw < 3; kw++) {
                    float v = xs[kd][lh + kh][lw + kw];
                    const float4* wr = (const float4*)ws[kd * 9 + kh * 3 + kw];
#pragma unroll
                    for (int o4 = 0; o4 < 16; o4++) {
                        float4 wv = wr[o4];
                        acc[o4 * 4 + 0] += v * wv.x;
                        acc[o4 * 4 + 1] += v * wv.y;
                        acc[o4 * 4 + 2] += v * wv.z;
                        acc[o4 * 4 + 3] += v * wv.w;
                    }
                }
    }

    int sp = t * 1024 + (h0 + lh) * 32 + lw;
#pragma unroll
    for (int o = 0; o < 64; o++) {
        float r = acc[o] + bias[ot + o];
        size_t oi = (size_t)(ot + o) * S_TOT + sp;
        if (resid) r += resid[oi];
        out[oi] = r;
    }
}

// ---------------- shared GEMM microkernel pieces ---------------------------
#define MICRO_FMA()                                                            \
    _Pragma("unroll")                                                          \
    for (int kk = 0; kk < 16; kk++) {                                          \
        float4 a = *(const float4*)&As[kk][ty * 4];                            \
        float4 b = *(const float4*)&Bs[kk][tx * 4];                            \
        acc[0][0] += a.x * b.x; acc[0][1] += a.x * b.y;                        \
        acc[0][2] += a.x * b.z; acc[0][3] += a.x * b.w;                        \
        acc[1][0] += a.y * b.x; acc[1][1] += a.y * b.y;                        \
        acc[1][2] += a.y * b.z; acc[1][3] += a.y * b.w;                        \
        acc[2][0] += a.z * b.x; acc[2][1] += a.z * b.y;                        \
        acc[2][2] += a.z * b.z; acc[2][3] += a.z * b.w;                        \
        acc[3][0] += a.w * b.x; acc[3][1] += a.w * b.y;                        \
        acc[3][2] += a.w * b.z; acc[3][3] += a.w * b.w;                        \
    }

// out[m][n] = sum_k X[k][m] * W[n][k] + bias[n]   (QKV projections)
// X: [512][8192] (channel-major activations), W: [512][512], out: [8192][512]
__global__ void gemm_proj_kernel(const float* __restrict__ X, const float* __restrict__ W,
                                 const float* __restrict__ bias, float* __restrict__ out) {
    __shared__ __align__(16) float As[16][68];
    __shared__ __align__(16) float Bs[16][68];
    int n0 = blockIdx.x * 64, m0 = blockIdx.y * 64;
    int tid = threadIdx.x, tx = tid & 15, ty = tid >> 4;
    int rr = tid >> 2, k4 = tid & 3;
    float acc[4][4] = {};
    for (int kt = 0; kt < 32; kt++) {
        __syncthreads();
#pragma unroll
        for (int r = 0; r < 4; r++) {
            int idx = tid + r * 256;
            int kk = idx >> 6, mm = idx & 63;
            As[kk][mm] = X[(size_t)(kt * 16 + kk) * S_TOT + m0 + mm];
        }
        float4 wv = *(const float4*)&W[(size_t)(n0 + rr) * 512 + kt * 16 + k4 * 4];
        Bs[k4 * 4 + 0][rr] = wv.x;
        Bs[k4 * 4 + 1][rr] = wv.y;
        Bs[k4 * 4 + 2][rr] = wv.z;
        Bs[k4 * 4 + 3][rr] = wv.w;
        __syncthreads();
        MICRO_FMA();
    }
    float4 bv = *(const float4*)&bias[n0 + tx * 4];
#pragma unroll
    for (int i = 0; i < 4; i++) {
        float4 r;
        r.x = acc[i][0] + bv.x; r.y = acc[i][1] + bv.y;
        r.z = acc[i][2] + bv.z; r.w = acc[i][3] + bv.w;
        *(float4*)&out[(size_t)(m0 + ty * 4 + i) * 512 + n0 + tx * 4] = r;
    }
}

// S[q][k] = scale * sum_d Q[q][d]*K[k][d]; skip blocks with kframe > qframe
__global__ void gemm_scores_kernel(const float* __restrict__ Q, const float* __restrict__ Kd,
                                   float* __restrict__ S) {
    int n0 = blockIdx.x * 64, m0 = blockIdx.y * 64;
    if ((n0 >> 10) > (m0 >> 10)) return;  // frame-causal skip
    __shared__ __align__(16) float As[16][68];
    __shared__ __align__(16) float Bs[16][68];
    int tid = threadIdx.x, tx = tid & 15, ty = tid >> 4;
    int rr = tid >> 2, k4 = tid & 3;
    float acc[4][4] = {};
    for (int kt = 0; kt < 32; kt++) {
        __syncthreads();
        float4 qv = *(const float4*)&Q[(size_t)(m0 + rr) * 512 + kt * 16 + k4 * 4];
        As[k4 * 4 + 0][rr] = qv.x; As[k4 * 4 + 1][rr] = qv.y;
        As[k4 * 4 + 2][rr] = qv.z; As[k4 * 4 + 3][rr] = qv.w;
        float4 kv = *(const float4*)&Kd[(size_t)(n0 + rr) * 512 + kt * 16 + k4 * 4];
        Bs[k4 * 4 + 0][rr] = kv.x; Bs[k4 * 4 + 1][rr] = kv.y;
        Bs[k4 * 4 + 2][rr] = kv.z; Bs[k4 * 4 + 3][rr] = kv.w;
        __syncthreads();
        MICRO_FMA();
    }
    const float scale = 0.04419417382415922f;  // 512^-0.5
#pragma unroll
    for (int i = 0; i < 4; i++) {
        float4 r;
        r.x = acc[i][0] * scale; r.y = acc[i][1] * scale;
        r.z = acc[i][2] * scale; r.w = acc[i][3] * scale;
        *(float4*)&S[(size_t)(m0 + ty * 4 + i) * S_TOT + n0 + tx * 4] = r;
    }
}

// Row softmax over the allowed (frame-causal) prefix; values kept in registers.
__global__ void softmax_kernel(float* __restrict__ S) {
    __shared__ float red[256];
    int q = blockIdx.x;
    int L = ((q >> 10) + 1) << 10;  // (frame+1)*1024
    int n = L >> 8;                 // chunks of 256, <= 32
    float* row = S + (size_t)q * S_TOT;
    float v[32];
    float mx = -1e30f;
#pragma unroll
    for (int i = 0; i < 32; i++)
        if (i < n) { v[i] = row[i * 256 + threadIdx.x]; mx = fmaxf(mx, v[i]); }
    red[threadIdx.x] = mx;
    __syncthreads();
    for (int off = 128; off > 0; off >>= 1) {
        if (threadIdx.x < off) red[threadIdx.x] = fmaxf(red[threadIdx.x], red[threadIdx.x + off]);
        __syncthreads();
    }
    mx = red[0];
    __syncthreads();
    float s = 0.f;
#pragma unroll
    for (int i = 0; i < 32; i++)
        if (i < n) { v[i] = expf(v[i] - mx); s += v[i]; }
    red[threadIdx.x] = s;
    __syncthreads();
    for (int off = 128; off > 0; off >>= 1) {
        if (threadIdx.x < off) red[threadIdx.x] += red[threadIdx.x + off];
        __syncthreads();
    }
    float inv = 1.f / red[0];
#pragma unroll
    for (int i = 0; i < 32; i++)
        if (i < n) row[i * 256 + threadIdx.x] = v[i] * inv;
}

// O[q][d] = sum_{k<Lq} P[q][k] * V[k][d]
__global__ void gemm_pv_kernel(const float* __restrict__ P, const float* __restrict__ V,
                               float* __restrict__ out) {
    __shared__ __align__(16) float As[16][68];
    __shared__ __align__(16) float Bs[16][68];
    int n0 = blockIdx.x * 64, m0 = blockIdx.y * 64;
    int ktiles = ((((m0 >> 10) + 1) << 10) >> 4);  // allowed K range / 16
    int tid = threadIdx.x, tx = tid & 15, ty = tid >> 4;
    int rr = tid >> 2, k4 = tid & 3;
    float acc[4][4] = {};
    for (int kt = 0; kt < ktiles; kt++) {
        __syncthreads();
        float4 pv = *(const float4*)&P[(size_t)(m0 + rr) * S_TOT + kt * 16 + k4 * 4];
        As[k4 * 4 + 0][rr] = pv.x; As[k4 * 4 + 1][rr] = pv.y;
        As[k4 * 4 + 2][rr] = pv.z; As[k4 * 4 + 3][rr] = pv.w;
#pragma unroll
        for (int r = 0; r < 4; r++) {
            int idx = tid + r * 256;
            int kk = idx >> 6, nn = idx & 63;
            Bs[kk][nn] = V[(size_t)(kt * 16 + kk) * 512 + n0 + nn];
        }
        __syncthreads();
        MICRO_FMA();
    }
#pragma unroll
    for (int i = 0; i < 4; i++) {
        float4 r;
        r.x = acc[i][0]; r.y = acc[i][1]; r.z = acc[i][2]; r.w = acc[i][3];
        *(float4*)&out[(size_t)(m0 + ty * 4 + i) * 512 + n0 + tx * 4] = r;
    }
}

// out[c][s] = sum_d A[s][d]*Wo[c][d] + bo[c] + resid[c][s]   (transposed write)
__global__ void gemm_oproj_kernel(const float* __restrict__ A, const float* __restrict__ W,
                                  const float* __restrict__ bias, const float* __restrict__ resid,
                                  float* __restrict__ out) {
    __shared__ __align__(16) float As[16][68];
    __shared__ __align__(16) float Bs[16][68];
    int n0 = blockIdx.x * 64, m0 = blockIdx.y * 64;
    int tid = threadIdx.x, tx = tid & 15, ty = tid >> 4;
    int rr = tid >> 2, k4 = tid & 3;
    float acc[4][4] = {};
    for (int kt = 0; kt < 32; kt++) {
        __syncthreads();
        float4 av = *(const float4*)&A[(size_t)(m0 + rr) * 512 + kt * 16 + k4 * 4];
        As[k4 * 4 + 0][rr] = av.x; As[k4 * 4 + 1][rr] = av.y;
        As[k4 * 4 + 2][rr] = av.z; As[k4 * 4 + 3][rr] = av.w;
        float4 wv = *(const float4*)&W[(size_t)(n0 + rr) * 512 + kt * 16 + k4 * 4];
        Bs[k4 * 4 + 0][rr] = wv.x; Bs[k4 * 4 + 1][rr] = wv.y;
        Bs[k4 * 4 + 2][rr] = wv.z; Bs[k4 * 4 + 3][rr] = wv.w;
        __syncthreads();
        MICRO_FMA();
    }
#pragma unroll
    for (int j = 0; j < 4; j++) {
        int n = n0 + tx * 4 + j;
        float bn = bias[n];
        float4 rv = *(const float4*)&resid[(size_t)n * S_TOT + m0 + ty * 4];
        float4 r;
        r.x = acc[0][j] + bn + rv.x;
        r.y = acc[1][j] + bn + rv.y;
        r.z = acc[2][j] + bn + rv.z;
        r.w = acc[3][j] + bn + rv.w;
        *(float4*)&out[(size_t)n * S_TOT + m0 + ty * 4] = r;
    }
}

// ---------------------------- launcher -------------------------------------
extern "C" void kernel_launch(void* const* d_in, const int* in_sizes, int n_in,
                              void* d_out, int out_size) {
    (void)in_sizes; (void)n_in; (void)out_size;
    const float* x      = (const float*)d_in[0];
    const float* r0_n1s = (const float*)d_in[1];
    const float* r0_n1b = (const float*)d_in[2];
    const float* r0_w1  = (const float*)d_in[3];
    const float* r0_b1  = (const float*)d_in[4];
    const float* r0_n2s = (const float*)d_in[5];
    const float* r0_n2b = (const float*)d_in[6];
    const float* r0_w2  = (const float*)d_in[7];
    const float* r0_b2  = (const float*)d_in[8];
    const float* r1_n1s = (const float*)d_in[9];
    const float* r1_n1b = (const float*)d_in[10];
    const float* r1_w1  = (const float*)d_in[11];
    const float* r1_b1  = (const float*)d_in[12];
    const float* r1_n2s = (const float*)d_in[13];
    const float* r1_n2b = (const float*)d_in[14];
    const float* r1_w2  = (const float*)d_in[15];
    const float* r1_b2  = (const float*)d_in[16];
    const float* a_gns  = (const float*)d_in[17];
    const float* a_gnb  = (const float*)d_in[18];
    const float* wq = (const float*)d_in[19];
    const float* bq = (const float*)d_in[20];
    const float* wk = (const float*)d_in[21];
    const float* bk = (const float*)d_in[22];
    const float* wv = (const float*)d_in[23];
    const float* bv = (const float*)d_in[24];
    const float* wo = (const float*)d_in[25];
    const float* bo = (const float*)d_in[26];
    float* out = (float*)d_out;

    float *b0, *b1, *b2, *qb, *kb, *vb, *sc;
    cudaGetSymbolAddress((void**)&b0, g_buf0);
    cudaGetSymbolAddress((void**)&b1, g_buf1);
    cudaGetSymbolAddress((void**)&b2, g_buf2);
    cudaGetSymbolAddress((void**)&qb, g_q);
    cudaGetSymbolAddress((void**)&kb, g_k);
    cudaGetSymbolAddress((void**)&vb, g_v);
    cudaGetSymbolAddress((void**)&sc, g_scores);

    dim3 cgrid(8, 8, 4);       // otile, t, hblock
    dim3 pgrid(8, 128);        // n-tiles, m-tiles

    // ---- resnet block 0 ----
    gn_stats_kernel<<<32, 512>>>(x);
    gn_apply_kernel<<<4096, 256>>>(x, b0, r0_n1s, r0_n1b, 1);
    conv3d_kernel<<<cgrid, 256>>>(b0, r0_w1, r0_b1, nullptr, b1);
    gn_stats_kernel<<<32, 512>>>(b1);
    gn_apply_kernel<<<4096, 256>>>(b1, b0, r0_n2s, r0_n2b, 1);
    conv3d_kernel<<<cgrid, 256>>>(b0, r0_w2, r0_b2, x, b2);   // b2 = h (resnet0 out)

    // ---- causal frame attention ----
    gn_stats_kernel<<<32, 512>>>(b2);
    gn_apply_kernel<<<4096, 256>>>(b2, b0, a_gns, a_gnb, 0);  // b0 = xn  [c][s]
    gemm_proj_kernel<<<pgrid, 256>>>(b0, wq, bq, qb);
    gemm_proj_kernel<<<pgrid, 256>>>(b0, wk, bk, kb);
    gemm_proj_kernel<<<pgrid, 256>>>(b0, wv, bv, vb);
    gemm_scores_kernel<<<dim3(128, 128), 256>>>(qb, kb, sc);
    softmax_kernel<<<8192, 256>>>(sc);
    gemm_pv_kernel<<<pgrid, 256>>>(sc, vb, b1);               // b1 = attn O [s][d]
    gemm_oproj_kernel<<<pgrid, 256>>>(b1, wo, bo, b2, b0);    // b0 = attn out [c][s]

    // ---- resnet block 1 ----
    gn_stats_kernel<<<32, 512>>>(b0);
    gn_apply_kernel<<<4096, 256>>>(b0, b1, r1_n1s, r1_n1b, 1);
    conv3d_kernel<<<cgrid, 256>>>(b1, r1_w1, r1_b1, nullptr, b2);
    gn_stats_kernel<<<32, 512>>>(b2);
    gn_apply_kernel<<<4096, 256>>>(b2, b1, r1_n2s, r1_n2b, 1);
    conv3d_kernel<<<cgrid, 256>>>(b1, r1_w2, r1_b2, b0, out);
}

// round 2
// speedup vs baseline: 3.6971x; 3.6971x over previous
#include <cuda_runtime.h>
#include <math.h>
#include <stdint.h>

#define S_TOT 8192           // T*H*W = 8*32*32
#define CCH   512
#define NELEM (CCH * S_TOT)  // 4,194,304
#define PAD_PER_C 11560      // 10*34*34
#define KDIM 13824           // 512*27

// ---------------- scratch (device globals: allocation-free) ----------------
__device__ float g_buf0[NELEM];
__device__ float g_buf1[NELEM];
__device__ float g_buf2[NELEM];
__device__ float g_q[NELEM];
__device__ float g_k[NELEM];
__device__ float g_v[NELEM];
__device__ float g_scores[(size_t)S_TOT * S_TOT];  // 256 MB
__device__ float g_pad[CCH * PAD_PER_C];           // padded conv input
__device__ float g_wT[KDIM * CCH];                 // transposed conv weights
__device__ float g_mean[32];
__device__ float g_rstd[32];

// ---------------- tf32 MMA primitives --------------------------------------
__device__ __forceinline__ void mma_tf32(float c[4], uint32_t a0, uint32_t a1,
                                         uint32_t a2, uint32_t a3,
                                         uint32_t b0, uint32_t b1) {
    asm volatile(
        "mma.sync.aligned.m16n8k8.row.col.f32.tf32.tf32.f32 "
        "{%0,%1,%2,%3}, {%4,%5,%6,%7}, {%8,%9}, {%0,%1,%2,%3};\n"
        : "+f"(c[0]), "+f"(c[1]), "+f"(c[2]), "+f"(c[3])
        : "r"(a0), "r"(a1), "r"(a2), "r"(a3), "r"(b0), "r"(b1));
}
__device__ __forceinline__ uint32_t f2tf32(float x) {
    uint32_t r;
    asm("cvt.rna.tf32.f32 %0, %1;" : "=r"(r) : "f"(x));
    return r;
}

// warp-tile compute: 8 warps (2M x 4N), warp = 64x32, stage K = 16 (2 x k8)
#define MMA_COMPUTE(buf)                                                     \
    _Pragma("unroll")                                                        \
    for (int ks = 0; ks < 2; ks++) {                                         \
        uint32_t af[4][4], bf[4][2];                                         \
        _Pragma("unroll")                                                    \
        for (int i2 = 0; i2 < 4; i2++) {                                     \
            af[i2][0] = As[buf][ks * 8 + tig][mw + i2 * 16 + grp];           \
            af[i2][1] = As[buf][ks * 8 + tig][mw + i2 * 16 + grp + 8];       \
            af[i2][2] = As[buf][ks * 8 + tig + 4][mw + i2 * 16 + grp];       \
            af[i2][3] = As[buf][ks * 8 + tig + 4][mw + i2 * 16 + grp + 8];   \
        }                                                                    \
        _Pragma("unroll")                                                    \
        for (int j2 = 0; j2 < 4; j2++) {                                     \
            bf[j2][0] = Bs[buf][ks * 8 + tig][nw + j2 * 8 + grp];            \
            bf[j2][1] = Bs[buf][ks * 8 + tig + 4][nw + j2 * 8 + grp];        \
        }                                                                    \
        _Pragma("unroll")                                                    \
        for (int i2 = 0; i2 < 4; i2++)                                       \
            _Pragma("unroll")                                                \
            for (int j2 = 0; j2 < 4; j2++)                                   \
                mma_tf32(c[i2][j2], af[i2][0], af[i2][1], af[i2][2],         \
                         af[i2][3], bf[j2][0], bf[j2][1]);                   \
    }

// ---------------- GroupNorm stats ------------------------------------------
__global__ void gn_stats_kernel(const float* __restrict__ x) {
    __shared__ float red[512];
    int g = blockIdx.x;
    const float* base = x + (size_t)g * 16 * S_TOT;
    const int N = 16 * S_TOT;
    float s = 0.f;
    for (int i = threadIdx.x; i < N; i += 512) s += base[i];
    red[threadIdx.x] = s;
    __syncthreads();
    for (int off = 256; off > 0; off >>= 1) {
        if (threadIdx.x < off) red[threadIdx.x] += red[threadIdx.x + off];
        __syncthreads();
    }
    float mean = red[0] * (1.f / (float)N);
    __syncthreads();
    float ss = 0.f;
    for (int i = threadIdx.x; i < N; i += 512) {
        float d = base[i] - mean;
        ss += d * d;
    }
    red[threadIdx.x] = ss;
    __syncthreads();
    for (int off = 256; off > 0; off >>= 1) {
        if (threadIdx.x < off) red[threadIdx.x] += red[threadIdx.x + off];
        __syncthreads();
    }
    if (threadIdx.x == 0) {
        g_mean[g] = mean;
        g_rstd[g] = rsqrtf(red[0] * (1.f / (float)N) + 1e-6f);
    }
}

// ---------------- GroupNorm apply (+SiLU) ----------------------------------
__global__ void gn_apply_kernel(const float* __restrict__ x, float* __restrict__ y,
                                const float* __restrict__ sc, const float* __restrict__ bi,
                                int do_silu) {
    int i4 = blockIdx.x * blockDim.x + threadIdx.x;
    int c = i4 >> 11;
    int g = c >> 4;
    float rstd = g_rstd[g];
    float a = sc[c] * rstd;
    float b = bi[c] - g_mean[g] * a;
    float4 v = ((const float4*)x)[i4];
    float4 r;
    r.x = a * v.x + b;
    r.y = a * v.y + b;
    r.z = a * v.z + b;
    r.w = a * v.w + b;
    if (do_silu) {
        r.x = r.x / (1.f + expf(-r.x));
        r.y = r.y / (1.f + expf(-r.y));
        r.z = r.z / (1.f + expf(-r.z));
        r.w = r.w / (1.f + expf(-r.w));
    }
    ((float4*)y)[i4] = r;
}

// ---------------- conv input pre-pad (replicate; causal t) ------------------
__global__ void pad_kernel(const float* __restrict__ in, float* __restrict__ pad) {
    int idx = blockIdx.x * 256 + threadIdx.x;
    if (idx >= CCH * PAD_PER_C) return;
    int ci = idx / PAD_PER_C, r = idx - ci * PAD_PER_C;
    int tp = r / 1156, r2 = r - tp * 1156;
    int hp = r2 / 34, wp = r2 - hp * 34;
    int t = tp - 2; t = t < 0 ? 0 : t;
    int h = hp - 1; h = h < 0 ? 0 : (h > 31 ? 31 : h);
    int w = wp - 1; w = w < 0 ? 0 : (w > 31 ? 31 : w);
    pad[idx] = in[(size_t)ci * S_TOT + t * 1024 + h * 32 + w];
}

// ---------------- weight transpose: w[co][k] -> wT[k][co] -------------------
__global__ void wtrans_kernel(const float* __restrict__ w, float* __restrict__ wT) {
    __shared__ float tile[32][33];
    int k0 = blockIdx.x * 32, c0 = blockIdx.y * 32;
    int x = threadIdx.x, y = threadIdx.y;  // 32 x 8
#pragma unroll
    for (int i = 0; i < 32; i += 8)
        tile[y + i][x] = w[(size_t)(c0 + y + i) * KDIM + k0 + x];
    __syncthreads();
#pragma unroll
    for (int i = 0; i < 32; i += 8)
        wT[(size_t)(k0 + y + i) * CCH + c0 + x] = tile[x][y + i];
}

// ---------------- Conv3d as implicit GEMM (tf32 MMA) ------------------------
// M=512 (co), N=8192 (spatial), K=13824 (ci*27+tap). CTA 128x128, BK=16.
__global__ void __launch_bounds__(256, 2)
conv_mma_kernel(const float* __restrict__ pad, const float* __restrict__ wT,
                const float* __restrict__ bias, const float* __restrict__ resid,
                float* __restrict__ out) {
    __shared__ uint32_t As[2][16][136];
    __shared__ uint32_t Bs[2][16][136];
    const int tid = threadIdx.x, lane = tid & 31, wid = tid >> 5;
    const int tig = lane & 3, grp = lane >> 2;
    const int mw = (wid >> 2) * 64, nw = (wid & 3) * 32;
    const int n0 = blockIdx.x * 128, m0 = blockIdx.y * 128;
    const int t = n0 >> 10, h0 = (n0 >> 5) & 31;
    const int a_row = tid >> 4, a_col = (tid & 15) * 8;
    const int b_k = tid >> 5, b_lane = tid & 31;

    float c[4][4][4];
#pragma unroll
    for (int i = 0; i < 4; i++)
#pragma unroll
        for (int j = 0; j < 4; j++)
#pragma unroll
            for (int q = 0; q < 4; q++) c[i][j][q] = 0.f;

    float4 arg0, arg1;
    float brg[8];

#define CONV_LDG(kt) {                                                       \
    int kb = (kt) * 16;                                                      \
    const float* ap = &wT[(size_t)(kb + a_row) * CCH + m0 + a_col];          \
    arg0 = *(const float4*)ap;                                               \
    arg1 = *(const float4*)(ap + 4);                                         \
    _Pragma("unroll")                                                        \
    for (int u = 0; u < 2; u++) {                                            \
        int k = kb + b_k + u * 8;                                            \
        int ci = k / 27, tap = k - ci * 27;                                  \
        int kd = tap / 9, r2 = tap - kd * 9;                                 \
        int kh = r2 / 3, kw = r2 - kh * 3;                                   \
        const float* bp = &pad[(size_t)ci * PAD_PER_C + (t + kd) * 1156 +    \
                               (h0 + kh) * 34 + b_lane + kw];                \
        _Pragma("unroll")                                                    \
        for (int r = 0; r < 4; r++) brg[u * 4 + r] = bp[r * 34];             \
    } }

#define CONV_STS(buf) {                                                      \
    uint4 s0, s1;                                                            \
    s0.x = f2tf32(arg0.x); s0.y = f2tf32(arg0.y);                            \
    s0.z = f2tf32(arg0.z); s0.w = f2tf32(arg0.w);                            \
    s1.x = f2tf32(arg1.x); s1.y = f2tf32(arg1.y);                            \
    s1.z = f2tf32(arg1.z); s1.w = f2tf32(arg1.w);                            \
    *(uint4*)&As[buf][a_row][a_col] = s0;                                    \
    *(uint4*)&As[buf][a_row][a_col + 4] = s1;                                \
    _Pragma("unroll")                                                        \
    for (int u = 0; u < 2; u++)                                              \
        _Pragma("unroll")                                                    \
        for (int r = 0; r < 4; r++)                                          \
            Bs[buf][b_k + u * 8][r * 32 + b_lane] = f2tf32(brg[u * 4 + r]);  \
    }

    CONV_LDG(0);
    CONV_STS(0);
    __syncthreads();
    const int KT = KDIM / 16;  // 864
#pragma unroll 1
    for (int kt = 0; kt < KT; kt++) {
        int cur = kt & 1;
        if (kt + 1 < KT) CONV_LDG(kt + 1);
        MMA_COMPUTE(cur);
        if (kt + 1 < KT) CONV_STS(cur ^ 1);
        __syncthreads();
    }

#pragma unroll
    for (int i = 0; i < 4; i++)
#pragma unroll
        for (int half = 0; half < 2; half++) {
            int co = m0 + mw + i * 16 + grp + half * 8;
            float bv = bias[co];
            size_t rowbase = (size_t)co * S_TOT + n0;
#pragma unroll
            for (int j = 0; j < 4; j++) {
                int col = nw + j * 8 + 2 * tig;
                float2 v;
                v.x = c[i][j][half * 2 + 0] + bv;
                v.y = c[i][j][half * 2 + 1] + bv;
                if (resid) {
                    v.x += resid[rowbase + col];
                    v.y += resid[rowbase + col + 1];
                }
                *(float2*)&out[rowbase + col] = v;
            }
        }
}

// ---------------- Scores: S = scale * Q K^T (tf32, frame-causal skip) -------
__global__ void __launch_bounds__(256, 2)
scores_mma_kernel(const float* __restrict__ Q, const float* __restrict__ Kd,
                  float* __restrict__ S) {
    const int n0 = blockIdx.x * 128, m0 = blockIdx.y * 128;
    if ((n0 >> 10) > (m0 >> 10)) return;
    __shared__ uint32_t As[2][16][136];
    __shared__ uint32_t Bs[2][16][136];
    const int tid = threadIdx.x, lane = tid & 31, wid = tid >> 5;
    const int tig = lane & 3, grp = lane >> 2;
    const int mw = (wid >> 2) * 64, nw = (wid & 3) * 32;
    const int mm = tid >> 1, kk0 = (tid & 1) * 8;

    float c[4][4][4];
#pragma unroll
    for (int i = 0; i < 4; i++)
#pragma unroll
        for (int j = 0; j < 4; j++)
#pragma unroll
            for (int q = 0; q < 4; q++) c[i][j][q] = 0.f;

    float4 aq0, aq1, bq0, bq1;

#define SC_LDG(kt) {                                                         \
    int kb = (kt) * 16;                                                      \
    const float* qp = &Q[(size_t)(m0 + mm) * 512 + kb + kk0];                \
    aq0 = *(const float4*)qp; aq1 = *(const float4*)(qp + 4);                \
    const float* kp = &Kd[(size_t)(n0 + mm) * 512 + kb + kk0];               \
    bq0 = *(const float4*)kp; bq1 = *(const float4*)(kp + 4); }

#define SC_STS(buf) {                                                        \
    As[buf][kk0 + 0][mm] = f2tf32(aq0.x);                                    \
    As[buf][kk0 + 1][mm] = f2tf32(aq0.y);                                    \
    As[buf][kk0 + 2][mm] = f2tf32(aq0.z);                                    \
    As[buf][kk0 + 3][mm] = f2tf32(aq0.w);                                    \
    As[buf][kk0 + 4][mm] = f2tf32(aq1.x);                                    \
    As[buf][kk0 + 5][mm] = f2tf32(aq1.y);                                    \
    As[buf][kk0 + 6][mm] = f2tf32(aq1.z);                                    \
    As[buf][kk0 + 7][mm] = f2tf32(aq1.w);                                    \
    Bs[buf][kk0 + 0][mm] = f2tf32(bq0.x);                                    \
    Bs[buf][kk0 + 1][mm] = f2tf32(bq0.y);                                    \
    Bs[buf][kk0 + 2][mm] = f2tf32(bq0.z);                                    \
    Bs[buf][kk0 + 3][mm] = f2tf32(bq0.w);                                    \
    Bs[buf][kk0 + 4][mm] = f2tf32(bq1.x);                                    \
    Bs[buf][kk0 + 5][mm] = f2tf32(bq1.y);                                    \
    Bs[buf][kk0 + 6][mm] = f2tf32(bq1.z);                                    \
    Bs[buf][kk0 + 7][mm] = f2tf32(bq1.w); }

    SC_LDG(0);
    SC_STS(0);
    __syncthreads();
    const int KT = 32;
#pragma unroll 1
    for (int kt = 0; kt < KT; kt++) {
        int cur = kt & 1;
        if (kt + 1 < KT) SC_LDG(kt + 1);
        MMA_COMPUTE(cur);
        if (kt + 1 < KT) SC_STS(cur ^ 1);
        __syncthreads();
    }

    const float scale = 0.04419417382415922f;  // 512^-0.5
#pragma unroll
    for (int i = 0; i < 4; i++)
#pragma unroll
        for (int half = 0; half < 2; half++) {
            int row = mw + i * 16 + grp + half * 8;
            size_t rowbase = (size_t)(m0 + row) * S_TOT + n0;
#pragma unroll
            for (int j = 0; j < 4; j++) {
                int col = nw + j * 8 + 2 * tig;
                float2 v;
                v.x = c[i][j][half * 2 + 0] * scale;
                v.y = c[i][j][half * 2 + 1] * scale;
                *(float2*)&S[rowbase + col] = v;
            }
        }
}

// ---------------- PV: O = P(prefix) * V (tf32) ------------------------------
__global__ void __launch_bounds__(256, 2)
pv_mma_kernel(const float* __restrict__ P, const float* __restrict__ V,
              float* __restrict__ out) {
    const int n0 = blockIdx.x * 128, m0 = blockIdx.y * 128;
    __shared__ uint32_t As[2][16][136];
    __shared__ uint32_t Bs[2][16][136];
    const int tid = threadIdx.x, lane = tid & 31, wid = tid >> 5;
    const int tig = lane & 3, grp = lane >> 2;
    const int mw = (wid >> 2) * 64, nw = (wid & 3) * 32;
    const int mm = tid >> 1, kk0 = (tid & 1) * 8;
    const int vrow = tid >> 4, vcol = (tid & 15) * 8;

    float c[4][4][4];
#pragma unroll
    for (int i = 0; i < 4; i++)
#pragma unroll
        for (int j = 0; j < 4; j++)
#pragma unroll
            for (int q = 0; q < 4; q++) c[i][j][q] = 0.f;

    float4 ap0, ap1, bv0, bv1;

#define PV_LDG(kt) {                                                         \
    int kb = (kt) * 16;                                                      \
    const float* pp = &P[(size_t)(m0 + mm) * S_TOT + kb + kk0];              \
    ap0 = *(const float4*)pp; ap1 = *(const float4*)(pp + 4);                \
    const float* vp = &V[(size_t)(kb + vrow) * 512 + n0 + vcol];             \
    bv0 = *(const float4*)vp; bv1 = *(const float4*)(vp + 4); }

#define PV_STS(buf) {                                                        \
    As[buf][kk0 + 0][mm] = f2tf32(ap0.x);                                    \
    As[buf][kk0 + 1][mm] = f2tf32(ap0.y);                                    \
    As[buf][kk0 + 2][mm] = f2tf32(ap0.z);                                    \
    As[buf][kk0 + 3][mm] = f2tf32(ap0.w);                                    \
    As[buf][kk0 + 4][mm] = f2tf32(ap1.x);                                    \
    As[buf][kk0 + 5][mm] = f2tf32(ap1.y);                                    \
    As[buf][kk0 + 6][mm] = f2tf32(ap1.z);                                    \
    As[buf][kk0 + 7][mm] = f2tf32(ap1.w);                                    \
    uint4 s0, s1;                                                            \
    s0.x = f2tf32(bv0.x); s0.y = f2tf32(bv0.y);                              \
    s0.z = f2tf32(bv0.z); s0.w = f2tf32(bv0.w);                              \
    s1.x = f2tf32(bv1.x); s1.y = f2tf32(bv1.y);                              \
    s1.z = f2tf32(bv1.z); s1.w = f2tf32(bv1.w);                              \
    *(uint4*)&Bs[buf][vrow][vcol] = s0;                                      \
    *(uint4*)&Bs[buf][vrow][vcol + 4] = s1; }

    PV_LDG(0);
    PV_STS(0);
    __syncthreads();
    const int KT = ((m0 >> 10) + 1) * 64;  // allowed prefix / 16
#pragma unroll 1
    for (int kt = 0; kt < KT; kt++) {
        int cur = kt & 1;
        if (kt + 1 < KT) PV_LDG(kt + 1);
        MMA_COMPUTE(cur);
        if (kt + 1 < KT) PV_STS(cur ^ 1);
        __syncthreads();
    }

#pragma unroll
    for (int i = 0; i < 4; i++)
#pragma unroll
        for (int half = 0; half < 2; half++) {
            int row = mw + i * 16 + grp + half * 8;
            size_t rowbase = (size_t)(m0 + row) * 512 + n0;
#pragma unroll
            for (int j = 0; j < 4; j++) {
                int col = nw + j * 8 + 2 * tig;
                float2 v;
                v.x = c[i][j][half * 2 + 0];
                v.y = c[i][j][half * 2 + 1];
                *(float2*)&out[rowbase + col] = v;
            }
        }
}

// ---------------- fp32 64x64 microkernel (projections) ----------------------
#define MICRO_FMA()                                                            \
    _Pragma("unroll")                                                          \
    for (int kk = 0; kk < 16; kk++) {                                          \
        float4 a = *(const float4*)&Asf[kk][ty * 4];                           \
        float4 b = *(const float4*)&Bsf[kk][tx * 4];                           \
        acc[0][0] += a.x * b.x; acc[0][1] += a.x * b.y;                        \
        acc[0][2] += a.x * b.z; acc[0][3] += a.x * b.w;                        \
        acc[1][0] += a.y * b.x; acc[1][1] += a.y * b.y;                        \
        acc[1][2] += a.y * b.z; acc[1][3] += a.y * b.w;                        \
        acc[2][0] += a.z * b.x; acc[2][1] += a.z * b.y;                        \
        acc[2][2] += a.z * b.z; acc[2][3] += a.z * b.w;                        \
        acc[3][0] += a.w * b.x; acc[3][1] += a.w * b.y;                        \
        acc[3][2] += a.w * b.z; acc[3][3] += a.w * b.w;                        \
    }

// out[m][n] = sum_k X[k][m] * W[n][k] + bias[n]
__global__ void gemm_proj_kernel(const float* __restrict__ X, const float* __restrict__ W,
                                 const float* __restrict__ bias, float* __restrict__ out) {
    __shared__ __align__(16) float Asf[16][68];
    __shared__ __align__(16) float Bsf[16][68];
    int n0 = blockIdx.x * 64, m0 = blockIdx.y * 64;
    int tid = threadIdx.x, tx = tid & 15, ty = tid >> 4;
    int rr = tid >> 2, k4 = tid & 3;
    float acc[4][4] = {};
    for (int kt = 0; kt < 32; kt++) {
        __syncthreads();
#pragma unroll
        for (int r = 0; r < 4; r++) {
            int idx = tid + r * 256;
            int kk = idx >> 6, mmu = idx & 63;
            Asf[kk][mmu] = X[(size_t)(kt * 16 + kk) * S_TOT + m0 + mmu];
        }
        float4 wv = *(const float4*)&W[(size_t)(n0 + rr) * 512 + kt * 16 + k4 * 4];
        Bsf[k4 * 4 + 0][rr] = wv.x;
        Bsf[k4 * 4 + 1][rr] = wv.y;
        Bsf[k4 * 4 + 2][rr] = wv.z;
        Bsf[k4 * 4 + 3][rr] = wv.w;
        __syncthreads();
        MICRO_FMA();
    }
    float4 bvv = *(const float4*)&bias[n0 + tx * 4];
#pragma unroll
    for (int i = 0; i < 4; i++) {
        float4 r;
        r.x = acc[i][0] + bvv.x; r.y = acc[i][1] + bvv.y;
        r.z = acc[i][2] + bvv.z; r.w = acc[i][3] + bvv.w;
        *(float4*)&out[(size_t)(m0 + ty * 4 + i) * 512 + n0 + tx * 4] = r;
    }
}

// out[c][s] = sum_d A[s][d]*Wo[c][d] + bo[c] + resid[c][s]
__global__ void gemm_oproj_kernel(const float* __restrict__ A, const float* __restrict__ W,
                                  const float* __restrict__ bias, const float* __restrict__ resid,
                                  float* __restrict__ out) {
    __shared__ __align__(16) float Asf[16][68];
    __shared__ __align__(16) float Bsf[16][68];
    int n0 = blockIdx.x * 64, m0 = blockIdx.y * 64;
    int tid = threadIdx.x, tx = tid & 15, ty = tid >> 4;
    int rr = tid >> 2, k4 = tid & 3;
    float acc[4][4] = {};
    for (int kt = 0; kt < 32; kt++) {
        __syncthreads();
        float4 av = *(const float4*)&A[(size_t)(m0 + rr) * 512 + kt * 16 + k4 * 4];
        Asf[k4 * 4 + 0][rr] = av.x; Asf[k4 * 4 + 1][rr] = av.y;
        Asf[k4 * 4 + 2][rr] = av.z; Asf[k4 * 4 + 3][rr] = av.w;
        float4 wv = *(const float4*)&W[(size_t)(n0 + rr) * 512 + kt * 16 + k4 * 4];
        Bsf[k4 * 4 + 0][rr] = wv.x; Bsf[k4 * 4 + 1][rr] = wv.y;
        Bsf[k4 * 4 + 2][rr] = wv.z; Bsf[k4 * 4 + 3][rr] = wv.w;
        __syncthreads();
        MICRO_FMA();
    }
#pragma unroll
    for (int j = 0; j < 4; j++) {
        int n = n0 + tx * 4 + j;
        float bn = bias[n];
        float4 rv = *(const float4*)&resid[(size_t)n * S_TOT + m0 + ty * 4];
        float4 r;
        r.x = acc[0][j] + bn + rv.x;
        r.y = acc[1][j] + bn + rv.y;
        r.z = acc[2][j] + bn + rv.z;
        r.w = acc[3][j] + bn + rv.w;
        *(float4*)&out[(size_t)n * S_TOT + m0 + ty * 4] = r;
    }
}

// ---------------- Row softmax over allowed prefix ---------------------------
__global__ void softmax_kernel(float* __restrict__ S) {
    __shared__ float red[256];
    int q = blockIdx.x;
    int L = ((q >> 10) + 1) << 10;
    int n = L >> 8;
    float* row = S + (size_t)q * S_TOT;
    float v[32];
    float mx = -1e30f;
#pragma unroll
    for (int i = 0; i < 32; i++)
        if (i < n) { v[i] = row[i * 256 + threadIdx.x]; mx = fmaxf(mx, v[i]); }
    red[threadIdx.x] = mx;
    __syncthreads();
    for (int off = 128; off > 0; off >>= 1) {
        if (threadIdx.x < off) red[threadIdx.x] = fmaxf(red[threadIdx.x], red[threadIdx.x + off]);
        __syncthreads();
    }
    mx = red[0];
    __syncthreads();
    float s = 0.f;
#pragma unroll
    for (int i = 0; i < 32; i++)
        if (i < n) { v[i] = expf(v[i] - mx); s += v[i]; }
    red[threadIdx.x] = s;
    __syncthreads();
    for (int off = 128; off > 0; off >>= 1) {
        if (threadIdx.x < off) red[threadIdx.x] += red[threadIdx.x + off];
        __syncthreads();
    }
    float inv = 1.f / red[0];
#pragma unroll
    for (int i = 0; i < 32; i++)
        if (i < n) row[i * 256 + threadIdx.x] = v[i] * inv;
}

// ---------------------------- launcher -------------------------------------
extern "C" void kernel_launch(void* const* d_in, const int* in_sizes, int n_in,
                              void* d_out, int out_size) {
    (void)in_sizes; (void)n_in; (void)out_size;
    const float* x      = (const float*)d_in[0];
    const float* r0_n1s = (const float*)d_in[1];
    const float* r0_n1b = (const float*)d_in[2];
    const float* r0_w1  = (const float*)d_in[3];
    const float* r0_b1  = (const float*)d_in[4];
    const float* r0_n2s = (const float*)d_in[5];
    const float* r0_n2b = (const float*)d_in[6];
    const float* r0_w2  = (const float*)d_in[7];
    const float* r0_b2  = (const float*)d_in[8];
    const float* r1_n1s = (const float*)d_in[9];
    const float* r1_n1b = (const float*)d_in[10];
    const float* r1_w1  = (const float*)d_in[11];
    const float* r1_b1  = (const float*)d_in[12];
    const float* r1_n2s = (const float*)d_in[13];
    const float* r1_n2b = (const float*)d_in[14];
    const float* r1_w2  = (const float*)d_in[15];
    const float* r1_b2  = (const float*)d_in[16];
    const float* a_gns  = (const float*)d_in[17];
    const float* a_gnb  = (const float*)d_in[18];
    const float* wq = (const float*)d_in[19];
    const float* bq = (const float*)d_in[20];
    const float* wk = (const float*)d_in[21];
    const float* bk = (const float*)d_in[22];
    const float* wv = (const float*)d_in[23];
    const float* bv = (const float*)d_in[24];
    const float* wo = (const float*)d_in[25];
    const float* bo = (const float*)d_in[26];
    float* out = (float*)d_out;

    float *b0, *b1, *b2, *qb, *kb, *vb, *sc, *padb, *wTb;
    cudaGetSymbolAddress((void**)&b0, g_buf0);
    cudaGetSymbolAddress((void**)&b1, g_buf1);
    cudaGetSymbolAddress((void**)&b2, g_buf2);
    cudaGetSymbolAddress((void**)&qb, g_q);
    cudaGetSymbolAddress((void**)&kb, g_k);
    cudaGetSymbolAddress((void**)&vb, g_v);
    cudaGetSymbolAddress((void**)&sc, g_scores);
    cudaGetSymbolAddress((void**)&padb, g_pad);
    cudaGetSymbolAddress((void**)&wTb, g_wT);

    const int padblocks = (CCH * PAD_PER_C + 255) / 256;
    dim3 wtg(KDIM / 32, 16);
    dim3 wtb(32, 8);
    dim3 cgrid(64, 4);   // n-tiles (spatial), m-tiles (co)
    dim3 pgrid(8, 128);  // fp32 proj tiles

    // ---- resnet block 0 ----
    gn_stats_kernel<<<32, 512>>>(x);
    gn_apply_kernel<<<4096, 256>>>(x, b0, r0_n1s, r0_n1b, 1);
    pad_kernel<<<padblocks, 256>>>(b0, padb);
    wtrans_kernel<<<wtg, wtb>>>(r0_w1, wTb);
    conv_mma_kernel<<<cgrid, 256>>>(padb, wTb, r0_b1, nullptr, b1);
    gn_stats_kernel<<<32, 512>>>(b1);
    gn_apply_kernel<<<4096, 256>>>(b1, b0, r0_n2s, r0_n2b, 1);
    pad_kernel<<<padblocks, 256>>>(b0, padb);
    wtrans_kernel<<<wtg, wtb>>>(r0_w2, wTb);
    conv_mma_kernel<<<cgrid, 256>>>(padb, wTb, r0_b2, x, b2);  // b2 = resnet0 out

    // ---- causal frame attention ----
    gn_stats_kernel<<<32, 512>>>(b2);
    gn_apply_kernel<<<4096, 256>>>(b2, b0, a_gns, a_gnb, 0);   // b0 = xn [c][s]
    gemm_proj_kernel<<<pgrid, 256>>>(b0, wq, bq, qb);
    gemm_proj_kernel<<<pgrid, 256>>>(b0, wk, bk, kb);
    gemm_proj_kernel<<<pgrid, 256>>>(b0, wv, bv, vb);
    scores_mma_kernel<<<dim3(64, 64), 256>>>(qb, kb, sc);
    softmax_kernel<<<8192, 256>>>(sc);
    pv_mma_kernel<<<dim3(4, 64), 256>>>(sc, vb, b1);           // b1 = attn O [s][d]
    gemm_oproj_kernel<<<pgrid, 256>>>(b1, wo, bo, b2, b0);     // b0 = attn out [c][s]

    // ---- resnet block 1 ----
    gn_stats_kernel<<<32, 512>>>(b0);
    gn_apply_kernel<<<4096, 256>>>(b0, b1, r1_n1s, r1_n1b, 1);
    pad_kernel<<<padblocks, 256>>>(b1, padb);
    wtrans_kernel<<<wtg, wtb>>>(r1_w1, wTb);
    conv_mma_kernel<<<cgrid, 256>>>(padb, wTb, r1_b1, nullptr, b2);
    gn_stats_kernel<<<32, 512>>>(b2);
    gn_apply_kernel<<<4096, 256>>>(b2, b1, r1_n2s, r1_n2b, 1);
    pad_kernel<<<padblocks, 256>>>(b1, padb);
    wtrans_kernel<<<wtg, wtb>>>(r1_w2, wTb);
    conv_mma_kernel<<<cgrid, 256>>>(padb, wTb, r1_b2, b0, out);
}

// round 4
// speedup vs baseline: 4.2341x; 1.1452x over previous
#include <cuda_runtime.h>
#include <math.h>
#include <stdint.h>

#define S_TOT 8192           // T*H*W = 8*32*32
#define CCH   512
#define NELEM (CCH * S_TOT)  // 4,194,304
#define PAD_PER_C 11560      // 10*34*34
#define KDIM 13824           // 512*27

// ---------------- scratch (device globals: allocation-free) ----------------
__device__ float g_buf0[NELEM];
__device__ float g_buf1[NELEM];
__device__ float g_buf2[NELEM];
__device__ float g_q[NELEM];
__device__ float g_k[NELEM];
__device__ float g_v[NELEM];
__device__ float g_scores[(size_t)S_TOT * S_TOT];  // 256 MB
__device__ float g_pad[CCH * PAD_PER_C];           // padded conv input
__device__ float g_wT[KDIM * CCH];                 // transposed conv weights
__device__ float2 g_part[256];
__device__ float g_mean[32];
__device__ float g_rstd[32];

// ---------------- tf32 MMA primitives --------------------------------------
__device__ __forceinline__ void mma_tf32(float c[4], uint32_t a0, uint32_t a1,
                                         uint32_t a2, uint32_t a3,
                                         uint32_t b0, uint32_t b1) {
    asm volatile(
        "mma.sync.aligned.m16n8k8.row.col.f32.tf32.tf32.f32 "
        "{%0,%1,%2,%3}, {%4,%5,%6,%7}, {%8,%9}, {%0,%1,%2,%3};\n"
        : "+f"(c[0]), "+f"(c[1]), "+f"(c[2]), "+f"(c[3])
        : "r"(a0), "r"(a1), "r"(a2), "r"(a3), "r"(b0), "r"(b1));
}
__device__ __forceinline__ uint32_t f2tf32(float x) {
    uint32_t r;
    asm("cvt.rna.tf32.f32 %0, %1;" : "=r"(r) : "f"(x));
    return r;
}

// legacy (matrix-order smem) warp-tile compute for scores/pv kernels
#define MMA_COMPUTE(buf)                                                     \
    _Pragma("unroll")                                                        \
    for (int ks = 0; ks < 2; ks++) {                                         \
        uint32_t af[4][4], bf[4][2];                                         \
        _Pragma("unroll")                                                    \
        for (int i2 = 0; i2 < 4; i2++) {                                     \
            af[i2][0] = As[buf][ks * 8 + tig][mw + i2 * 16 + grp];           \
            af[i2][1] = As[buf][ks * 8 + tig][mw + i2 * 16 + grp + 8];       \
            af[i2][2] = As[buf][ks * 8 + tig + 4][mw + i2 * 16 + grp];       \
            af[i2][3] = As[buf][ks * 8 + tig + 4][mw + i2 * 16 + grp + 8];   \
        }                                                                    \
        _Pragma("unroll")                                                    \
        for (int j2 = 0; j2 < 4; j2++) {                                     \
            bf[j2][0] = Bs[buf][ks * 8 + tig][nw + j2 * 8 + grp];            \
            bf[j2][1] = Bs[buf][ks * 8 + tig + 4][nw + j2 * 8 + grp];        \
        }                                                                    \
        _Pragma("unroll")                                                    \
        for (int i2 = 0; i2 < 4; i2++)                                       \
            _Pragma("unroll")                                                \
            for (int j2 = 0; j2 < 4; j2++)                                   \
                mma_tf32(c[i2][j2], af[i2][0], af[i2][1], af[i2][2],         \
                         af[i2][3], bf[j2][0], bf[j2][1]);                   \
    }

// ---------------- GroupNorm stats: partial + finalize -----------------------
__global__ void gn_part_kernel(const float* __restrict__ x) {
    __shared__ float rs[256], rq[256];
    int g = blockIdx.x >> 3, ch = blockIdx.x & 7;
    const float* base = x + (size_t)g * 16 * S_TOT + ch * 16384;
    float s = 0.f, ss = 0.f;
    for (int i = threadIdx.x; i < 16384; i += 256) {
        float v = base[i];
        s += v;
        ss += v * v;
    }
    rs[threadIdx.x] = s;
    rq[threadIdx.x] = ss;
    __syncthreads();
    for (int off = 128; off > 0; off >>= 1) {
        if (threadIdx.x < off) {
            rs[threadIdx.x] += rs[threadIdx.x + off];
            rq[threadIdx.x] += rq[threadIdx.x + off];
        }
        __syncthreads();
    }
    if (threadIdx.x == 0) g_part[blockIdx.x] = make_float2(rs[0], rq[0]);
}

__global__ void gn_fin_kernel() {
    int g = threadIdx.x;
    if (g < 32) {
        float s = 0.f, ss = 0.f;
        for (int c = 0; c < 8; c++) {
            float2 p = g_part[g * 8 + c];
            s += p.x;
            ss += p.y;
        }
        float mean = s * (1.f / 131072.f);
        float var = ss * (1.f / 131072.f) - mean * mean;
        g_mean[g] = mean;
        g_rstd[g] = rsqrtf(var + 1e-6f);
    }
}

// ---------------- GroupNorm apply (+SiLU) ----------------------------------
__global__ void gn_apply_kernel(const float* __restrict__ x, float* __restrict__ y,
                                const float* __restrict__ sc, const float* __restrict__ bi,
                                int do_silu) {
    int i4 = blockIdx.x * blockDim.x + threadIdx.x;
    int c = i4 >> 11;
    int g = c >> 4;
    float rstd = g_rstd[g];
    float a = sc[c] * rstd;
    float b = bi[c] - g_mean[g] * a;
    float4 v = ((const float4*)x)[i4];
    float4 r;
    r.x = a * v.x + b;
    r.y = a * v.y + b;
    r.z = a * v.z + b;
    r.w = a * v.w + b;
    if (do_silu) {
        r.x = r.x / (1.f + expf(-r.x));
        r.y = r.y / (1.f + expf(-r.y));
        r.z = r.z / (1.f + expf(-r.z));
        r.w = r.w / (1.f + expf(-r.w));
    }
    ((float4*)y)[i4] = r;
}

// ---------------- conv input pre-pad (replicate; causal t) ------------------
__global__ void pad_kernel(const float* __restrict__ in, float* __restrict__ pad) {
    int idx = blockIdx.x * 256 + threadIdx.x;
    if (idx >= CCH * PAD_PER_C) return;
    int ci = idx / PAD_PER_C, r = idx - ci * PAD_PER_C;
    int tp = r / 1156, r2 = r - tp * 1156;
    int hp = r2 / 34, wp = r2 - hp * 34;
    int t = tp - 2; t = t < 0 ? 0 : t;
    int h = hp - 1; h = h < 0 ? 0 : (h > 31 ? 31 : h);
    int w = wp - 1; w = w < 0 ? 0 : (w > 31 ? 31 : w);
    pad[idx] = in[(size_t)ci * S_TOT + t * 1024 + h * 32 + w];
}

// ---------------- weight transpose: w[co][k] -> wT[k][co] -------------------
__global__ void wtrans_kernel(const float* __restrict__ w, float* __restrict__ wT) {
    __shared__ float tile[32][33];
    int k0 = blockIdx.x * 32, c0 = blockIdx.y * 32;
    int x = threadIdx.x, y = threadIdx.y;  // 32 x 8
#pragma unroll
    for (int i = 0; i < 32; i += 8)
        tile[y + i][x] = w[(size_t)(c0 + y + i) * KDIM + k0 + x];
    __syncthreads();
#pragma unroll
    for (int i = 0; i < 32; i += 8)
        wT[(size_t)(k0 + y + i) * CCH + c0 + x] = tile[x][y + i];
}

// ---------------- Conv3d as implicit GEMM (tf32 MMA, fragment-layout smem) --
// M=512 (co), N=8192 (spatial), K=13824. CTA 128x128, BK=16, double buffer.
// Smem fragment layout:
//   A: Af[buf][k8][mtile*132 + lane*4 + reg]   (LDS.128 per fragment)
//   B: Bf[buf][k8][ntile*66  + lane*2 + reg]   (LDS.64  per fragment)
// element (kin,min): lane = (min&7)*4 + (kin&3); A reg = (kin>>2)*2 + (min>>3)
//                    B reg = kin>>2 (nin = n&7 -> lane part)
__global__ void __launch_bounds__(256, 2)
conv_mma_kernel(const float* __restrict__ pad, const float* __restrict__ wT,
                const float* __restrict__ bias, const float* __restrict__ resid,
                float* __restrict__ out) {
    __shared__ uint32_t Af[2][2][8 * 132];
    __shared__ uint32_t Bf[2][2][16 * 66];
    const int tid = threadIdx.x, lane = tid & 31, wid = tid >> 5;
    const int tig = lane & 3, grp = lane >> 2;
    const int mt0 = (wid >> 2) * 4, nt0 = (wid & 3) * 4;
    const int mw = (wid >> 2) * 64, nw = (wid & 3) * 32;
    const int n0 = blockIdx.x * 128, m0 = blockIdx.y * 128;
    const int t = n0 >> 10, h0 = (n0 >> 5) & 31;
    // A producer: a_row = k (0..15), a_col = 8 consecutive m
    const int a_row = tid >> 4, a_col = (tid & 15) * 8;
    const int a_k8 = a_row >> 3, a_kin = a_row & 7;
    const int a_mt = a_col >> 4;
    const int a_off = a_mt * 132 + (a_kin & 3) * 4 + ((a_kin >> 2) * 2 + ((a_col >> 3) & 1));
    // B producer: b_k = kin (0..7) for u in {0,1}; n = r*32 + b_lane
    const int b_k = tid >> 5, b_lane = tid & 31;
    const int b_off = (b_lane >> 3) * 66 + ((b_lane & 7) * 4 + (b_k & 3)) * 2 + (b_k >> 2);

    float c[4][4][4];
#pragma unroll
    for (int i = 0; i < 4; i++)
#pragma unroll
        for (int j = 0; j < 4; j++)
#pragma unroll
            for (int q = 0; q < 4; q++) c[i][j][q] = 0.f;

    float4 arg0, arg1;
    float brg[8];

#define CONV_LDG(kt) {                                                       \
    int kb = (kt) * 16;                                                      \
    const float* ap = &wT[(size_t)(kb + a_row) * CCH + m0 + a_col];          \
    arg0 = *(const float4*)ap;                                               \
    arg1 = *(const float4*)(ap + 4);                                         \
    _Pragma("unroll")                                                        \
    for (int u = 0; u < 2; u++) {                                            \
        int k = kb + b_k + u * 8;                                            \
        int ci = k / 27, tap = k - ci * 27;                                  \
        int kd = tap / 9, r2 = tap - kd * 9;                                 \
        int kh = r2 / 3, kw = r2 - kh * 3;                                   \
        const float* bp = &pad[(size_t)ci * PAD_PER_C + (t + kd) * 1156 +    \
                               (h0 + kh) * 34 + b_lane + kw];                \
        _Pragma("unroll")                                                    \
        for (int r = 0; r < 4; r++) brg[u * 4 + r] = bp[r * 34];             \
    } }

#define CONV_STS(buf) {                                                      \
    uint32_t* Ad = &Af[buf][a_k8][a_off];                                    \
    Ad[0]   = f2tf32(arg0.x); Ad[16]  = f2tf32(arg0.y);                      \
    Ad[32]  = f2tf32(arg0.z); Ad[48]  = f2tf32(arg0.w);                      \
    Ad[64]  = f2tf32(arg1.x); Ad[80]  = f2tf32(arg1.y);                      \
    Ad[96]  = f2tf32(arg1.z); Ad[112] = f2tf32(arg1.w);                      \
    _Pragma("unroll")                                                        \
    for (int u = 0; u < 2; u++)                                              \
        _Pragma("unroll")                                                    \
        for (int r = 0; r < 4; r++)                                          \
            Bf[buf][u][b_off + r * 264] = f2tf32(brg[u * 4 + r]);            \
    }

#define CONV_MMA(buf)                                                        \
    _Pragma("unroll")                                                        \
    for (int ks = 0; ks < 2; ks++) {                                         \
        uint4 av[4];                                                         \
        uint2 bvv[4];                                                        \
        _Pragma("unroll")                                                    \
        for (int i2 = 0; i2 < 4; i2++)                                       \
            av[i2] = *(const uint4*)&Af[buf][ks][(mt0 + i2) * 132 + lane * 4]; \
        _Pragma("unroll")                                                    \
        for (int j2 = 0; j2 < 4; j2++)                                       \
            bvv[j2] = *(const uint2*)&Bf[buf][ks][(nt0 + j2) * 66 + lane * 2]; \
        _Pragma("unroll")                                                    \
        for (int i2 = 0; i2 < 4; i2++)                                       \
            _Pragma("unroll")                                                \
            for (int j2 = 0; j2 < 4; j2++)                                   \
                mma_tf32(c[i2][j2], av[i2].x, av[i2].y, av[i2].z, av[i2].w,  \
                         bvv[j2].x, bvv[j2].y);                              \
    }

    CONV_LDG(0);
    CONV_STS(0);
    __syncthreads();
    const int KT = KDIM / 16;  // 864
#pragma unroll 1
    for (int kt = 0; kt < KT; kt++) {
        int cur = kt & 1;
        if (kt + 1 < KT) CONV_LDG(kt + 1);
        CONV_MMA(cur);
        if (kt + 1 < KT) CONV_STS(cur ^ 1);
        __syncthreads();
    }

#pragma unroll
    for (int i = 0; i < 4; i++)
#pragma unroll
        for (int half = 0; half < 2; half++) {
            int co = m0 + mw + i * 16 + grp + half * 8;
            float bv = bias[co];
            size_t rowbase = (size_t)co * S_TOT + n0;
#pragma unroll
            for (int j = 0; j < 4; j++) {
                int col = nw + j * 8 + 2 * tig;
                float2 v;
                v.x = c[i][j][half * 2 + 0] + bv;
                v.y = c[i][j][half * 2 + 1] + bv;
                if (resid) {
                    v.x += resid[rowbase + col];
                    v.y += resid[rowbase + col + 1];
                }
                *(float2*)&out[rowbase + col] = v;
            }
        }
}

// ---------------- Scores: S = scale * Q K^T (tf32, frame-causal skip) -------
__global__ void __launch_bounds__(256, 2)
scores_mma_kernel(const float* __restrict__ Q, const float* __restrict__ Kd,
                  float* __restrict__ S) {
    const int n0 = blockIdx.x * 128, m0 = blockIdx.y * 128;
    if ((n0 >> 10) > (m0 >> 10)) return;
    __shared__ uint32_t As[2][16][136];
    __shared__ uint32_t Bs[2][16][136];
    const int tid = threadIdx.x, lane = tid & 31, wid = tid >> 5;
    const int tig = lane & 3, grp = lane >> 2;
    const int mw = (wid >> 2) * 64, nw = (wid & 3) * 32;
    const int mm = tid >> 1, kk0 = (tid & 1) * 8;

    float c[4][4][4];
#pragma unroll
    for (int i = 0; i < 4; i++)
#pragma unroll
        for (int j = 0; j < 4; j++)
#pragma unroll
            for (int q = 0; q < 4; q++) c[i][j][q] = 0.f;

    float4 aq0, aq1, bq0, bq1;

#define SC_LDG(kt) {                                                         \
    int kb = (kt) * 16;                                                      \
    const float* qp = &Q[(size_t)(m0 + mm) * 512 + kb + kk0];                \
    aq0 = *(const float4*)qp; aq1 = *(const float4*)(qp + 4);                \
    const float* kp = &Kd[(size_t)(n0 + mm) * 512 + kb + kk0];               \
    bq0 = *(const float4*)kp; bq1 = *(const float4*)(kp + 4); }

#define SC_STS(buf) {                                                        \
    As[buf][kk0 + 0][mm] = f2tf32(aq0.x);                                    \
    As[buf][kk0 + 1][mm] = f2tf32(aq0.y);                                    \
    As[buf][kk0 + 2][mm] = f2tf32(aq0.z);                                    \
    As[buf][kk0 + 3][mm] = f2tf32(aq0.w);                                    \
    As[buf][kk0 + 4][mm] = f2tf32(aq1.x);                                    \
    As[buf][kk0 + 5][mm] = f2tf32(aq1.y);                                    \
    As[buf][kk0 + 6][mm] = f2tf32(aq1.z);                                    \
    As[buf][kk0 + 7][mm] = f2tf32(aq1.w);                                    \
    Bs[buf][kk0 + 0][mm] = f2tf32(bq0.x);                                    \
    Bs[buf][kk0 + 1][mm] = f2tf32(bq0.y);                                    \
    Bs[buf][kk0 + 2][mm] = f2tf32(bq0.z);                                    \
    Bs[buf][kk0 + 3][mm] = f2tf32(bq0.w);                                    \
    Bs[buf][kk0 + 4][mm] = f2tf32(bq1.x);                                    \
    Bs[buf][kk0 + 5][mm] = f2tf32(bq1.y);                                    \
    Bs[buf][kk0 + 6][mm] = f2tf32(bq1.z);                                    \
    Bs[buf][kk0 + 7][mm] = f2tf32(bq1.w); }

    SC_LDG(0);
    SC_STS(0);
    __syncthreads();
    const int KT = 32;
#pragma unroll 1
    for (int kt = 0; kt < KT; kt++) {
        int cur = kt & 1;
        if (kt + 1 < KT) SC_LDG(kt + 1);
        MMA_COMPUTE(cur);
        if (kt + 1 < KT) SC_STS(cur ^ 1);
        __syncthreads();
    }

    const float scale = 0.04419417382415922f;  // 512^-0.5
#pragma unroll
    for (int i = 0; i < 4; i++)
#pragma unroll
        for (int half = 0; half < 2; half++) {
            int row = mw + i * 16 + grp + half * 8;
            size_t rowbase = (size_t)(m0 + row) * S_TOT + n0;
#pragma unroll
            for (int j = 0; j < 4; j++) {
                int col = nw + j * 8 + 2 * tig;
                float2 v;
                v.x = c[i][j][half * 2 + 0] * scale;
                v.y = c[i][j][half * 2 + 1] * scale;
                *(float2*)&S[rowbase + col] = v;
            }
        }
}

// ---------------- PV: O = P(prefix) * V (tf32) ------------------------------
__global__ void __launch_bounds__(256, 2)
pv_mma_kernel(const float* __restrict__ P, const float* __restrict__ V,
              float* __restrict__ out) {
    const int n0 = blockIdx.x * 128, m0 = blockIdx.y * 128;
    __shared__ uint32_t As[2][16][136];
    __shared__ uint32_t Bs[2][16][136];
    const int tid = threadIdx.x, lane = tid & 31, wid = tid >> 5;
    const int tig = lane & 3, grp = lane >> 2;
    const int mw = (wid >> 2) * 64, nw = (wid & 3) * 32;
    const int mm = tid >> 1, kk0 = (tid & 1) * 8;
    const int vrow = tid >> 4, vcol = (tid & 15) * 8;

    float c[4][4][4];
#pragma unroll
    for (int i = 0; i < 4; i++)
#pragma unroll
        for (int j = 0; j < 4; j++)
#pragma unroll
            for (int q = 0; q < 4; q++) c[i][j][q] = 0.f;

    float4 ap0, ap1, bv0, bv1;

#define PV_LDG(kt) {                                                         \
    int kb = (kt) * 16;                                                      \
    const float* pp = &P[(size_t)(m0 + mm) * S_TOT + kb + kk0];              \
    ap0 = *(const float4*)pp; ap1 = *(const float4*)(pp + 4);                \
    const float* vp = &V[(size_t)(kb + vrow) * 512 + n0 + vcol];             \
    bv0 = *(const float4*)vp; bv1 = *(const float4*)(vp + 4); }

#define PV_STS(buf) {                                                        \
    As[buf][kk0 + 0][mm] = f2tf32(ap0.x);                                    \
    As[buf][kk0 + 1][mm] = f2tf32(ap0.y);                                    \
    As[buf][kk0 + 2][mm] = f2tf32(ap0.z);                                    \
    As[buf][kk0 + 3][mm] = f2tf32(ap0.w);                                    \
    As[buf][kk0 + 4][mm] = f2tf32(ap1.x);                                    \
    As[buf][kk0 + 5][mm] = f2tf32(ap1.y);                                    \
    As[buf][kk0 + 6][mm] = f2tf32(ap1.z);                                    \
    As[buf][kk0 + 7][mm] = f2tf32(ap1.w);                                    \
    uint4 s0, s1;                                                            \
    s0.x = f2tf32(bv0.x); s0.y = f2tf32(bv0.y);                              \
    s0.z = f2tf32(bv0.z); s0.w = f2tf32(bv0.w);                              \
    s1.x = f2tf32(bv1.x); s1.y = f2tf32(bv1.y);                              \
    s1.z = f2tf32(bv1.z); s1.w = f2tf32(bv1.w);                              \
    *(uint4*)&Bs[buf][vrow][vcol] = s0;                                      \
    *(uint4*)&Bs[buf][vrow][vcol + 4] = s1; }

    PV_LDG(0);
    PV_STS(0);
    __syncthreads();
    const int KT = ((m0 >> 10) + 1) * 64;  // allowed prefix / 16
#pragma unroll 1
    for (int kt = 0; kt < KT; kt++) {
        int cur = kt & 1;
        if (kt + 1 < KT) PV_LDG(kt + 1);
        MMA_COMPUTE(cur);
        if (kt + 1 < KT) PV_STS(cur ^ 1);
        __syncthreads();
    }

#pragma unroll
    for (int i = 0; i < 4; i++)
#pragma unroll
        for (int half = 0; half < 2; half++) {
            int row = mw + i * 16 + grp + half * 8;
            size_t rowbase = (size_t)(m0 + row) * 512 + n0;
#pragma unroll
            for (int j = 0; j < 4; j++) {
                int col = nw + j * 8 + 2 * tig;
                float2 v;
                v.x = c[i][j][half * 2 + 0];
                v.y = c[i][j][half * 2 + 1];
                *(float2*)&out[rowbase + col] = v;
            }
        }
}

// ---------------- fp32 64x64 microkernel (projections) ----------------------
#define MICRO_FMA()                                                            \
    _Pragma("unroll")                                                          \
    for (int kk = 0; kk < 16; kk++) {                                          \
        float4 a = *(const float4*)&Asf[kk][ty * 4];                           \
        float4 b = *(const float4*)&Bsf[kk][tx * 4];                           \
        acc[0][0] += a.x * b.x; acc[0][1] += a.x * b.y;                        \
        acc[0][2] += a.x * b.z; acc[0][3] += a.x * b.w;                        \
        acc[1][0] += a.y * b.x; acc[1][1] += a.y * b.y;                        \
        acc[1][2] += a.y * b.z; acc[1][3] += a.y * b.w;                        \
        acc[2][0] += a.z * b.x; acc[2][1] += a.z * b.y;                        \
        acc[2][2] += a.z * b.z; acc[2][3] += a.z * b.w;                        \
        acc[3][0] += a.w * b.x; acc[3][1] += a.w * b.y;                        \
        acc[3][2] += a.w * b.z; acc[3][3] += a.w * b.w;                        \
    }

// out[m][n] = sum_k X[k][m] * W[n][k] + bias[n]
__global__ void gemm_proj_kernel(const float* __restrict__ X, const float* __restrict__ W,
                                 const float* __restrict__ bias, float* __restrict__ out) {
    __shared__ __align__(16) float Asf[16][68];
    __shared__ __align__(16) float Bsf[16][68];
    int n0 = blockIdx.x * 64, m0 = blockIdx.y * 64;
    int tid = threadIdx.x, tx = tid & 15, ty = tid >> 4;
    int rr = tid >> 2, k4 = tid & 3;
    float acc[4][4] = {};
    for (int kt = 0; kt < 32; kt++) {
        __syncthreads();
#pragma unroll
        for (int r = 0; r < 4; r++) {
            int idx = tid + r * 256;
            int kk = idx >> 6, mmu = idx & 63;
            Asf[kk][mmu] = X[(size_t)(kt * 16 + kk) * S_TOT + m0 + mmu];
        }
        float4 wv = *(const float4*)&W[(size_t)(n0 + rr) * 512 + kt * 16 + k4 * 4];
        Bsf[k4 * 4 + 0][rr] = wv.x;
        Bsf[k4 * 4 + 1][rr] = wv.y;
        Bsf[k4 * 4 + 2][rr] = wv.z;
        Bsf[k4 * 4 + 3][rr] = wv.w;
        __syncthreads();
        MICRO_FMA();
    }
    float4 bvv = *(const float4*)&bias[n0 + tx * 4];
#pragma unroll
    for (int i = 0; i < 4; i++) {
        float4 r;
        r.x = acc[i][0] + bvv.x; r.y = acc[i][1] + bvv.y;
        r.z = acc[i][2] + bvv.z; r.w = acc[i][3] + bvv.w;
        *(float4*)&out[(size_t)(m0 + ty * 4 + i) * 512 + n0 + tx * 4] = r;
    }
}

// out[c][s] = sum_d A[s][d]*Wo[c][d] + bo[c] + resid[c][s]
__global__ void gemm_oproj_kernel(const float* __restrict__ A, const float* __restrict__ W,
                                  const float* __restrict__ bias, const float* __restrict__ resid,
                                  float* __restrict__ out) {
    __shared__ __align__(16) float Asf[16][68];
    __shared__ __align__(16) float Bsf[16][68];
    int n0 = blockIdx.x * 64, m0 = blockIdx.y * 64;
    int tid = threadIdx.x, tx = tid & 15, ty = tid >> 4;
    int rr = tid >> 2, k4 = tid & 3;
    float acc[4][4] = {};
    for (int kt = 0; kt < 32; kt++) {
        __syncthreads();
        float4 av = *(const float4*)&A[(size_t)(m0 + rr) * 512 + kt * 16 + k4 * 4];
        Asf[k4 * 4 + 0][rr] = av.x; Asf[k4 * 4 + 1][rr] = av.y;
        Asf[k4 * 4 + 2][rr] = av.z; Asf[k4 * 4 + 3][rr] = av.w;
        float4 wv = *(const float4*)&W[(size_t)(n0 + rr) * 512 + kt * 16 + k4 * 4];
        Bsf[k4 * 4 + 0][rr] = wv.x; Bsf[k4 * 4 + 1][rr] = wv.y;
        Bsf[k4 * 4 + 2][rr] = wv.z; Bsf[k4 * 4 + 3][rr] = wv.w;
        __syncthreads();
        MICRO_FMA();
    }
#pragma unroll
    for (int j = 0; j < 4; j++) {
        int n = n0 + tx * 4 + j;
        float bn = bias[n];
        float4 rv = *(const float4*)&resid[(size_t)n * S_TOT + m0 + ty * 4];
        float4 r;
        r.x = acc[0][j] + bn + rv.x;
        r.y = acc[1][j] + bn + rv.y;
        r.z = acc[2][j] + bn + rv.z;
        r.w = acc[3][j] + bn + rv.w;
        *(float4*)&out[(size_t)n * S_TOT + m0 + ty * 4] = r;
    }
}

// ---------------- Row softmax over allowed prefix ---------------------------
__global__ void softmax_kernel(float* __restrict__ S) {
    __shared__ float red[256];
    int q = blockIdx.x;
    int L = ((q >> 10) + 1) << 10;
    int n = L >> 8;
    float* row = S + (size_t)q * S_TOT;
    float v[32];
    float mx = -1e30f;
#pragma unroll
    for (int i = 0; i < 32; i++)
        if (i < n) { v[i] = row[i * 256 + threadIdx.x]; mx = fmaxf(mx, v[i]); }
    red[threadIdx.x] = mx;
    __syncthreads();
    for (int off = 128; off > 0; off >>= 1) {
        if (threadIdx.x < off) red[threadIdx.x] = fmaxf(red[threadIdx.x], red[threadIdx.x + off]);
        __syncthreads();
    }
    mx = red[0];
    __syncthreads();
    float s = 0.f;
#pragma unroll
    for (int i = 0; i < 32; i++)
        if (i < n) { v[i] = expf(v[i] - mx); s += v[i]; }
    red[threadIdx.x] = s;
    __syncthreads();
    for (int off = 128; off > 0; off >>= 1) {
        if (threadIdx.x < off) red[threadIdx.x] += red[threadIdx.x + off];
        __syncthreads();
    }
    float inv = 1.f / red[0];
#pragma unroll
    for (int i = 0; i < 32; i++)
        if (i < n) row[i * 256 + threadIdx.x] = v[i] * inv;
}

// ---------------------------- launcher -------------------------------------
extern "C" void kernel_launch(void* const* d_in, const int* in_sizes, int n_in,
                              void* d_out, int out_size) {
    (void)in_sizes; (void)n_in; (void)out_size;
    const float* x      = (const float*)d_in[0];
    const float* r0_n1s = (const float*)d_in[1];
    const float* r0_n1b = (const float*)d_in[2];
    const float* r0_w1  = (const float*)d_in[3];
    const float* r0_b1  = (const float*)d_in[4];
    const float* r0_n2s = (const float*)d_in[5];
    const float* r0_n2b = (const float*)d_in[6];
    const float* r0_w2  = (const float*)d_in[7];
    const float* r0_b2  = (const float*)d_in[8];
    const float* r1_n1s = (const float*)d_in[9];
    const float* r1_n1b = (const float*)d_in[10];
    const float* r1_w1  = (const float*)d_in[11];
    const float* r1_b1  = (const float*)d_in[12];
    const float* r1_n2s = (const float*)d_in[13];
    const float* r1_n2b = (const float*)d_in[14];
    const float* r1_w2  = (const float*)d_in[15];
    const float* r1_b2  = (const float*)d_in[16];
    const float* a_gns  = (const float*)d_in[17];
    const float* a_gnb  = (const float*)d_in[18];
    const float* wq = (const float*)d_in[19];
    const float* bq = (const float*)d_in[20];
    const float* wk = (const float*)d_in[21];
    const float* bk = (const float*)d_in[22];
    const float* wv = (const float*)d_in[23];
    const float* bv = (const float*)d_in[24];
    const float* wo = (const float*)d_in[25];
    const float* bo = (const float*)d_in[26];
    float* out = (float*)d_out;

    float *b0, *b1, *b2, *qb, *kb, *vb, *sc, *padb, *wTb;
    cudaGetSymbolAddress((void**)&b0, g_buf0);
    cudaGetSymbolAddress((void**)&b1, g_buf1);
    cudaGetSymbolAddress((void**)&b2, g_buf2);
    cudaGetSymbolAddress((void**)&qb, g_q);
    cudaGetSymbolAddress((void**)&kb, g_k);
    cudaGetSymbolAddress((void**)&vb, g_v);
    cudaGetSymbolAddress((void**)&sc, g_scores);
    cudaGetSymbolAddress((void**)&padb, g_pad);
    cudaGetSymbolAddress((void**)&wTb, g_wT);

    const int padblocks = (CCH * PAD_PER_C + 255) / 256;
    dim3 wtg(KDIM / 32, 16);
    dim3 wtb(32, 8);
    dim3 cgrid(64, 4);   // n-tiles (spatial), m-tiles (co)
    dim3 pgrid(8, 128);  // fp32 proj tiles

#define GN_STATS(ptr) do { \
    gn_part_kernel<<<256, 256>>>(ptr); \
    gn_fin_kernel<<<1, 32>>>(); } while (0)

    // ---- resnet block 0 ----
    GN_STATS(x);
    gn_apply_kernel<<<4096, 256>>>(x, b0, r0_n1s, r0_n1b, 1);
    pad_kernel<<<padblocks, 256>>>(b0, padb);
    wtrans_kernel<<<wtg, wtb>>>(r0_w1, wTb);
    conv_mma_kernel<<<cgrid, 256>>>(padb, wTb, r0_b1, nullptr, b1);
    GN_STATS(b1);
    gn_apply_kernel<<<4096, 256>>>(b1, b0, r0_n2s, r0_n2b, 1);
    pad_kernel<<<padblocks, 256>>>(b0, padb);
    wtrans_kernel<<<wtg, wtb>>>(r0_w2, wTb);
    conv_mma_kernel<<<cgrid, 256>>>(padb, wTb, r0_b2, x, b2);  // b2 = resnet0 out

    // ---- causal frame attention ----
    GN_STATS(b2);
    gn_apply_kernel<<<4096, 256>>>(b2, b0, a_gns, a_gnb, 0);   // b0 = xn [c][s]
    gemm_proj_kernel<<<pgrid, 256>>>(b0, wq, bq, qb);
    gemm_proj_kernel<<<pgrid, 256>>>(b0, wk, bk, kb);
    gemm_proj_kernel<<<pgrid, 256>>>(b0, wv, bv, vb);
    scores_mma_kernel<<<dim3(64, 64), 256>>>(qb, kb, sc);
    softmax_kernel<<<8192, 256>>>(sc);
    pv_mma_kernel<<<dim3(4, 64), 256>>>(sc, vb, b1);           // b1 = attn O [s][d]
    gemm_oproj_kernel<<<pgrid, 256>>>(b1, wo, bo, b2, b0);     // b0 = attn out [c][s]

    // ---- resnet block 1 ----
    GN_STATS(b0);
    gn_apply_kernel<<<4096, 256>>>(b0, b1, r1_n1s, r1_n1b, 1);
    pad_kernel<<<padblocks, 256>>>(b1, padb);
    wtrans_kernel<<<wtg, wtb>>>(r1_w1, wTb);
    conv_mma_kernel<<<cgrid, 256>>>(padb, wTb, r1_b1, nullptr, b2);
    GN_STATS(b2);
    gn_apply_kernel<<<4096, 256>>>(b2, b1, r1_n2s, r1_n2b, 1);
    pad_kernel<<<padblocks, 256>>>(b1, padb);
    wtrans_kernel<<<wtg, wtb>>>(r1_w2, wTb);
    conv_mma_kernel<<<cgrid, 256>>>(padb, wTb, r1_b2, b0, out);
}

// round 6
// speedup vs baseline: 6.3674x; 1.5039x over previous
#include <cuda_runtime.h>
#include <cuda_fp16.h>
#include <math.h>
#include <stdint.h>

#define S_TOT 8192           // T*H*W = 8*32*32
#define CCH   512
#define NELEM (CCH * S_TOT)  // 4,194,304
#define PAD_PER_C 11560      // 10*34*34
#define KDIM 13824           // 512*27
#define KT32 432             // KDIM/32

// ---------------- scratch (device globals: allocation-free) ----------------
__device__ float g_buf0[NELEM];
__device__ float g_buf1[NELEM];
__device__ float g_buf2[NELEM];
__device__ float g_q[NELEM];
__device__ float g_k[NELEM];
__device__ float g_v[NELEM];
__device__ float g_scores[(size_t)S_TOT * S_TOT];  // 256 MB
__device__ float g_pad[CCH * PAD_PER_C];           // padded conv input
__device__ uint32_t g_wfr[KDIM * CCH / 2];         // fp16 fragment-packed weights
__device__ int   g_offB[KDIM];                     // per-k pad offset table
__device__ float2 g_part[256];
__device__ float g_mean[32];
__device__ float g_rstd[32];

// ---------------- MMA primitives -------------------------------------------
__device__ __forceinline__ void mma_tf32(float c[4], uint32_t a0, uint32_t a1,
                                         uint32_t a2, uint32_t a3,
                                         uint32_t b0, uint32_t b1) {
    asm volatile(
        "mma.sync.aligned.m16n8k8.row.col.f32.tf32.tf32.f32 "
        "{%0,%1,%2,%3}, {%4,%5,%6,%7}, {%8,%9}, {%0,%1,%2,%3};\n"
        : "+f"(c[0]), "+f"(c[1]), "+f"(c[2]), "+f"(c[3])
        : "r"(a0), "r"(a1), "r"(a2), "r"(a3), "r"(b0), "r"(b1));
}
__device__ __forceinline__ void mma_f16(float c[4], uint32_t a0, uint32_t a1,
                                        uint32_t a2, uint32_t a3,
                                        uint32_t b0, uint32_t b1) {
    asm volatile(
        "mma.sync.aligned.m16n8k16.row.col.f32.f16.f16.f32 "
        "{%0,%1,%2,%3}, {%4,%5,%6,%7}, {%8,%9}, {%0,%1,%2,%3};\n"
        : "+f"(c[0]), "+f"(c[1]), "+f"(c[2]), "+f"(c[3])
        : "r"(a0), "r"(a1), "r"(a2), "r"(a3), "r"(b0), "r"(b1));
}
__device__ __forceinline__ uint32_t f2tf32(float x) {
    uint32_t r;
    asm("cvt.rna.tf32.f32 %0, %1;" : "=r"(r) : "f"(x));
    return r;
}
__device__ __forceinline__ uint32_t f2h2(float lo, float hi) {
    __half2 h = __floats2half2_rn(lo, hi);
    return *(uint32_t*)&h;
}

// legacy (matrix-order smem) tf32 warp-tile compute for scores/pv kernels
#define MMA_COMPUTE(buf)                                                     \
    _Pragma("unroll")                                                        \
    for (int ks = 0; ks < 2; ks++) {                                         \
        uint32_t af[4][4], bf[4][2];                                         \
        _Pragma("unroll")                                                    \
        for (int i2 = 0; i2 < 4; i2++) {                                     \
            af[i2][0] = As[buf][ks * 8 + tig][mw + i2 * 16 + grp];           \
            af[i2][1] = As[buf][ks * 8 + tig][mw + i2 * 16 + grp + 8];       \
            af[i2][2] = As[buf][ks * 8 + tig + 4][mw + i2 * 16 + grp];       \
            af[i2][3] = As[buf][ks * 8 + tig + 4][mw + i2 * 16 + grp + 8];   \
        }                                                                    \
        _Pragma("unroll")                                                    \
        for (int j2 = 0; j2 < 4; j2++) {                                     \
            bf[j2][0] = Bs[buf][ks * 8 + tig][nw + j2 * 8 + grp];            \
            bf[j2][1] = Bs[buf][ks * 8 + tig + 4][nw + j2 * 8 + grp];        \
        }                                                                    \
        _Pragma("unroll")                                                    \
        for (int i2 = 0; i2 < 4; i2++)                                       \
            _Pragma("unroll")                                                \
            for (int j2 = 0; j2 < 4; j2++)                                   \
                mma_tf32(c[i2][j2], af[i2][0], af[i2][1], af[i2][2],         \
                         af[i2][3], bf[j2][0], bf[j2][1]);                   \
    }

// ---------------- GroupNorm stats: partial + finalize -----------------------
__global__ void gn_part_kernel(const float* __restrict__ x) {
    __shared__ float rs[256], rq[256];
    int g = blockIdx.x >> 3, ch = blockIdx.x & 7;
    const float* base = x + (size_t)g * 16 * S_TOT + ch * 16384;
    float s = 0.f, ss = 0.f;
    for (int i = threadIdx.x; i < 16384; i += 256) {
        float v = base[i];
        s += v;
        ss += v * v;
    }
    rs[threadIdx.x] = s;
    rq[threadIdx.x] = ss;
    __syncthreads();
    for (int off = 128; off > 0; off >>= 1) {
        if (threadIdx.x < off) {
            rs[threadIdx.x] += rs[threadIdx.x + off];
            rq[threadIdx.x] += rq[threadIdx.x + off];
        }
        __syncthreads();
    }
    if (threadIdx.x == 0) g_part[blockIdx.x] = make_float2(rs[0], rq[0]);
}

__global__ void gn_fin_kernel() {
    int g = threadIdx.x;
    if (g < 32) {
        float s = 0.f, ss = 0.f;
        for (int c = 0; c < 8; c++) {
            float2 p = g_part[g * 8 + c];
            s += p.x;
            ss += p.y;
        }
        float mean = s * (1.f / 131072.f);
        float var = ss * (1.f / 131072.f) - mean * mean;
        g_mean[g] = mean;
        g_rstd[g] = rsqrtf(var + 1e-6f);
    }
}

// ---------------- GroupNorm apply (+SiLU) ----------------------------------
__global__ void gn_apply_kernel(const float* __restrict__ x, float* __restrict__ y,
                                const float* __restrict__ sc, const float* __restrict__ bi,
                                int do_silu) {
    int i4 = blockIdx.x * blockDim.x + threadIdx.x;
    int c = i4 >> 11;
    int g = c >> 4;
    float rstd = g_rstd[g];
    float a = sc[c] * rstd;
    float b = bi[c] - g_mean[g] * a;
    float4 v = ((const float4*)x)[i4];
    float4 r;
    r.x = a * v.x + b;
    r.y = a * v.y + b;
    r.z = a * v.z + b;
    r.w = a * v.w + b;
    if (do_silu) {
        r.x = r.x / (1.f + expf(-r.x));
        r.y = r.y / (1.f + expf(-r.y));
        r.z = r.z / (1.f + expf(-r.z));
        r.w = r.w / (1.f + expf(-r.w));
    }
    ((float4*)y)[i4] = r;
}

// ---------------- conv input pre-pad (replicate; causal t) ------------------
__global__ void pad_kernel(const float* __restrict__ in, float* __restrict__ pad) {
    int idx = blockIdx.x * 256 + threadIdx.x;
    if (idx >= CCH * PAD_PER_C) return;
    int ci = idx / PAD_PER_C, r = idx - ci * PAD_PER_C;
    int tp = r / 1156, r2 = r - tp * 1156;
    int hp = r2 / 34, wp = r2 - hp * 34;
    int t = tp - 2; t = t < 0 ? 0 : t;
    int h = hp - 1; h = h < 0 ? 0 : (h > 31 ? 31 : h);
    int w = wp - 1; w = w < 0 ? 0 : (w > 31 ? 31 : w);
    pad[idx] = in[(size_t)ci * S_TOT + t * 1024 + h * 32 + w];
}

// ---------------- per-k offset table for the conv B gather ------------------
__global__ void offb_kernel() {
    int k = blockIdx.x * 256 + threadIdx.x;
    if (k >= KDIM) return;
    int ci = k / 27, tap = k - ci * 27;
    int kd = tap / 9, r2 = tap - kd * 9;
    int kh = r2 / 3, kw = r2 - kh * 3;
    g_offB[k] = ci * PAD_PER_C + kd * 1156 + kh * 34 + kw;
}

// ---------------- weight fragment pack: w[co][k] -> fp16 A-fragment images --
// b32 idx = ((mt*KT32+kt)*16 + ks*8 + mtile)*128 + lane*4 + reg
// min = (reg&1)*8 + (lane>>2); kin = (reg>>1)*8 + 2*(lane&3) + h(half)
__global__ void wfrag_kernel(const float* __restrict__ w, uint32_t* __restrict__ dst) {
    int idx = blockIdx.x * 256 + threadIdx.x;
    if (idx >= KDIM * CCH / 2) return;
    int reg = idx & 3, lane = (idx >> 2) & 31;
    int r2 = idx >> 7;
    int mtile = r2 & 7, ks = (r2 >> 3) & 1;
    int ktm = r2 >> 4;
    int kt = ktm % KT32, mt = ktm / KT32;
    int m = mt * 128 + mtile * 16 + (reg & 1) * 8 + (lane >> 2);
    int k = kt * 32 + ks * 16 + (reg >> 1) * 8 + 2 * (lane & 3);
    const float* src = &w[(size_t)m * KDIM + k];
    dst[idx] = f2h2(src[0], src[1]);
}

// ---------------- Conv3d implicit GEMM, fp16 m16n8k16 -----------------------
// M=128(co)/CTA, N=128(spatial)/CTA, BK=32 (2 k16 steps), 432 iters, dbuf.
// A smem: linear copy of gmem fragment image (2048 b32 per buf).
// B smem: fragment order, (ks*16+ntile)*66 + lane_c*2 + reg.
__global__ void __launch_bounds__(256, 2)
conv_hmma_kernel(const float* __restrict__ pad, const uint32_t* __restrict__ wfr,
                 const float* __restrict__ bias, const float* __restrict__ resid,
                 float* __restrict__ out) {
    __shared__ __align__(16) uint32_t Asm[2][2048];
    __shared__ __align__(16) uint32_t Bsm[2][2112];
    const int tid = threadIdx.x, lane = tid & 31, wid = tid >> 5;
    const int tig = lane & 3, grp = lane >> 2;
    const int mt0 = (wid >> 2) * 4, nt0 = (wid & 3) * 4;
    const int mw = (wid >> 2) * 64, nw = (wid & 3) * 32;
    const int n0 = blockIdx.x * 128, m0 = blockIdx.y * 128;
    const int mt = blockIdx.y;
    const int t = n0 >> 10, h0 = (n0 >> 5) & 31;
    const int kp = tid >> 5;  // 0..7: k-pairs kp (ks=0) and kp (ks=1)

    // B gather spatial bases: r = n block (4 h-rows), lane = w col
    int sb[4];
#pragma unroll
    for (int r = 0; r < 4; r++) sb[r] = t * 1156 + (h0 + r) * 34 + lane;
    // B STS b32 offsets (ks=0); ks=1 adds 16*66
    int boff[4];
#pragma unroll
    for (int r = 0; r < 4; r++) {
        int ntile = r * 4 + (lane >> 3), nin = lane & 7;
        boff[r] = ntile * 66 + (nin * 4 + (kp & 3)) * 2 + (kp >> 2);
    }

    float c[4][4][4];
#pragma unroll
    for (int i = 0; i < 4; i++)
#pragma unroll
        for (int j = 0; j < 4; j++)
#pragma unroll
            for (int q = 0; q < 4; q++) c[i][j][q] = 0.f;

    uint4 areg0, areg1;
    float brg[4][4];

#define CV_LDG(kt) {                                                         \
    const uint4* asrc = (const uint4*)wfr + (size_t)(mt * KT32 + (kt)) * 512;\
    areg0 = asrc[tid];                                                       \
    areg1 = asrc[tid + 256];                                                 \
    int kb = (kt) * 32 + 2 * kp;                                             \
    int o00 = g_offB[kb], o01 = g_offB[kb + 1];                              \
    int o10 = g_offB[kb + 16], o11 = g_offB[kb + 17];                        \
    _Pragma("unroll")                                                        \
    for (int r = 0; r < 4; r++) {                                            \
        brg[r][0] = pad[o00 + sb[r]];                                        \
        brg[r][1] = pad[o01 + sb[r]];                                        \
        brg[r][2] = pad[o10 + sb[r]];                                        \
        brg[r][3] = pad[o11 + sb[r]];                                        \
    } }

#define CV_STS(buf) {                                                        \
    ((uint4*)&Asm[buf][0])[tid] = areg0;                                     \
    ((uint4*)&Asm[buf][0])[tid + 256] = areg1;                               \
    _Pragma("unroll")                                                        \
    for (int r = 0; r < 4; r++) {                                            \
        Bsm[buf][boff[r]] = f2h2(brg[r][0], brg[r][1]);                      \
        Bsm[buf][boff[r] + 16 * 66] = f2h2(brg[r][2], brg[r][3]);            \
    } }

#define CV_MMA(buf)                                                          \
    _Pragma("unroll")                                                        \
    for (int ks = 0; ks < 2; ks++) {                                         \
        uint4 av[4];                                                         \
        uint2 bv2[4];                                                        \
        _Pragma("unroll")                                                    \
        for (int i2 = 0; i2 < 4; i2++)                                       \
            av[i2] = *(const uint4*)&Asm[buf][(ks * 8 + mt0 + i2) * 128 + lane * 4]; \
        _Pragma("unroll")                                                    \
        for (int j2 = 0; j2 < 4; j2++)                                       \
            bv2[j2] = *(const uint2*)&Bsm[buf][(ks * 16 + nt0 + j2) * 66 + lane * 2]; \
        _Pragma("unroll")                                                    \
        for (int i2 = 0; i2 < 4; i2++)                                       \
            _Pragma("unroll")                                                \
            for (int j2 = 0; j2 < 4; j2++)                                   \
                mma_f16(c[i2][j2], av[i2].x, av[i2].y, av[i2].z, av[i2].w,   \
                        bv2[j2].x, bv2[j2].y);                               \
    }

    CV_LDG(0);
    CV_STS(0);
    __syncthreads();
#pragma unroll 1
    for (int kt = 0; kt < KT32; kt++) {
        int cur = kt & 1;
        if (kt + 1 < KT32) CV_LDG(kt + 1);
        CV_MMA(cur);
        if (kt + 1 < KT32) CV_STS(cur ^ 1);
        __syncthreads();
    }

#pragma unroll
    for (int i = 0; i < 4; i++)
#pragma unroll
        for (int half = 0; half < 2; half++) {
            int co = m0 + mw + i * 16 + grp + half * 8;
            float bv = bias[co];
            size_t rowbase = (size_t)co * S_TOT + n0;
#pragma unroll
            for (int j = 0; j < 4; j++) {
                int col = nw + j * 8 + 2 * tig;
                float2 v;
                v.x = c[i][j][half * 2 + 0] + bv;
                v.y = c[i][j][half * 2 + 1] + bv;
                if (resid) {
                    v.x += resid[rowbase + col];
                    v.y += resid[rowbase + col + 1];
                }
                *(float2*)&out[rowbase + col] = v;
            }
        }
}

// ---------------- Scores: S = scale * Q K^T (tf32, frame-causal skip) -------
__global__ void __launch_bounds__(256, 2)
scores_mma_kernel(const float* __restrict__ Q, const float* __restrict__ Kd,
                  float* __restrict__ S) {
    const int n0 = blockIdx.x * 128, m0 = blockIdx.y * 128;
    if ((n0 >> 10) > (m0 >> 10)) return;
    __shared__ uint32_t As[2][16][136];
    __shared__ uint32_t Bs[2][16][136];
    const int tid = threadIdx.x, lane = tid & 31, wid = tid >> 5;
    const int tig = lane & 3, grp = lane >> 2;
    const int mw = (wid >> 2) * 64, nw = (wid & 3) * 32;
    const int mm = tid >> 1, kk0 = (tid & 1) * 8;

    float c[4][4][4];
#pragma unroll
    for (int i = 0; i < 4; i++)
#pragma unroll
        for (int j = 0; j < 4; j++)
#pragma unroll
            for (int q = 0; q < 4; q++) c[i][j][q] = 0.f;

    float4 aq0, aq1, bq0, bq1;

#define SC_LDG(kt) {                                                         \
    int kb = (kt) * 16;                                                      \
    const float* qp = &Q[(size_t)(m0 + mm) * 512 + kb + kk0];                \
    aq0 = *(const float4*)qp; aq1 = *(const float4*)(qp + 4);                \
    const float* kp2 = &Kd[(size_t)(n0 + mm) * 512 + kb + kk0];              \
    bq0 = *(const float4*)kp2; bq1 = *(const float4*)(kp2 + 4); }

#define SC_STS(buf) {                                                        \
    As[buf][kk0 + 0][mm] = f2tf32(aq0.x);                                    \
    As[buf][kk0 + 1][mm] = f2tf32(aq0.y);                                    \
    As[buf][kk0 + 2][mm] = f2tf32(aq0.z);                                    \
    As[buf][kk0 + 3][mm] = f2tf32(aq0.w);                                    \
    As[buf][kk0 + 4][mm] = f2tf32(aq1.x);                                    \
    As[buf][kk0 + 5][mm] = f2tf32(aq1.y);                                    \
    As[buf][kk0 + 6][mm] = f2tf32(aq1.z);                                    \
    As[buf][kk0 + 7][mm] = f2tf32(aq1.w);                                    \
    Bs[buf][kk0 + 0][mm] = f2tf32(bq0.x);                                    \
    Bs[buf][kk0 + 1][mm] = f2tf32(bq0.y);                                    \
    Bs[buf][kk0 + 2][mm] = f2tf32(bq0.z);                                    \
    Bs[buf][kk0 + 3][mm] = f2tf32(bq0.w);                                    \
    Bs[buf][kk0 + 4][mm] = f2tf32(bq1.x);                                    \
    Bs[buf][kk0 + 5][mm] = f2tf32(bq1.y);                                    \
    Bs[buf][kk0 + 6][mm] = f2tf32(bq1.z);                                    \
    Bs[buf][kk0 + 7][mm] = f2tf32(bq1.w); }

    SC_LDG(0);
    SC_STS(0);
    __syncthreads();
    const int KT = 32;
#pragma unroll 1
    for (int kt = 0; kt < KT; kt++) {
        int cur = kt & 1;
        if (kt + 1 < KT) SC_LDG(kt + 1);
        MMA_COMPUTE(cur);
        if (kt + 1 < KT) SC_STS(cur ^ 1);
        __syncthreads();
    }

    const float scale = 0.04419417382415922f;  // 512^-0.5
#pragma unroll
    for (int i = 0; i < 4; i++)
#pragma unroll
        for (int half = 0; half < 2; half++) {
            int row = mw + i * 16 + grp + half * 8;
            size_t rowbase = (size_t)(m0 + row) * S_TOT + n0;
#pragma unroll
            for (int j = 0; j < 4; j++) {
                int col = nw + j * 8 + 2 * tig;
                float2 v;
                v.x = c[i][j][half * 2 + 0] * scale;
                v.y = c[i][j][half * 2 + 1] * scale;
                *(float2*)&S[rowbase + col] = v;
            }
        }
}

// ---------------- PV: O = P(prefix) * V (tf32) ------------------------------
__global__ void __launch_bounds__(256, 2)
pv_mma_kernel(const float* __restrict__ P, const float* __restrict__ V,
              float* __restrict__ out) {
    const int n0 = blockIdx.x * 128, m0 = blockIdx.y * 128;
    __shared__ uint32_t As[2][16][136];
    __shared__ uint32_t Bs[2][16][136];
    const int tid = threadIdx.x, lane = tid & 31, wid = tid >> 5;
    const int tig = lane & 3, grp = lane >> 2;
    const int mw = (wid >> 2) * 64, nw = (wid & 3) * 32;
    const int mm = tid >> 1, kk0 = (tid & 1) * 8;
    const int vrow = tid >> 4, vcol = (tid & 15) * 8;

    float c[4][4][4];
#pragma unroll
    for (int i = 0; i < 4; i++)
#pragma unroll
        for (int j = 0; j < 4; j++)
#pragma unroll
            for (int q = 0; q < 4; q++) c[i][j][q] = 0.f;

    float4 ap0, ap1, bv0, bv1;

#define PV_LDG(kt) {                                                         \
    int kb = (kt) * 16;                                                      \
    const float* pp = &P[(size_t)(m0 + mm) * S_TOT + kb + kk0];              \
    ap0 = *(const float4*)pp; ap1 = *(const float4*)(pp + 4);                \
    const float* vp = &V[(size_t)(kb + vrow) * 512 + n0 + vcol];             \
    bv0 = *(const float4*)vp; bv1 = *(const float4*)(vp + 4); }

#define PV_STS(buf) {                                                        \
    As[buf][kk0 + 0][mm] = f2tf32(ap0.x);                                    \
    As[buf][kk0 + 1][mm] = f2tf32(ap0.y);                                    \
    As[buf][kk0 + 2][mm] = f2tf32(ap0.z);                                    \
    As[buf][kk0 + 3][mm] = f2tf32(ap0.w);                                    \
    As[buf][kk0 + 4][mm] = f2tf32(ap1.x);                                    \
    As[buf][kk0 + 5][mm] = f2tf32(ap1.y);                                    \
    As[buf][kk0 + 6][mm] = f2tf32(ap1.z);                                    \
    As[buf][kk0 + 7][mm] = f2tf32(ap1.w);                                    \
    uint4 s0, s1;                                                            \
    s0.x = f2tf32(bv0.x); s0.y = f2tf32(bv0.y);                              \
    s0.z = f2tf32(bv0.z); s0.w = f2tf32(bv0.w);                              \
    s1.x = f2tf32(bv1.x); s1.y = f2tf32(bv1.y);                              \
    s1.z = f2tf32(bv1.z); s1.w = f2tf32(bv1.w);                              \
    *(uint4*)&Bs[buf][vrow][vcol] = s0;                                      \
    *(uint4*)&Bs[buf][vrow][vcol + 4] = s1; }

    PV_LDG(0);
    PV_STS(0);
    __syncthreads();
    const int KT = ((m0 >> 10) + 1) * 64;  // allowed prefix / 16
#pragma unroll 1
    for (int kt = 0; kt < KT; kt++) {
        int cur = kt & 1;
        if (kt + 1 < KT) PV_LDG(kt + 1);
        MMA_COMPUTE(cur);
        if (kt + 1 < KT) PV_STS(cur ^ 1);
        __syncthreads();
    }

#pragma unroll
    for (int i = 0; i < 4; i++)
#pragma unroll
        for (int half = 0; half < 2; half++) {
            int row = mw + i * 16 + grp + half * 8;
            size_t rowbase = (size_t)(m0 + row) * 512 + n0;
#pragma unroll
            for (int j = 0; j < 4; j++) {
                int col = nw + j * 8 + 2 * tig;
                float2 v;
                v.x = c[i][j][half * 2 + 0];
                v.y = c[i][j][half * 2 + 1];
                *(float2*)&out[rowbase + col] = v;
            }
        }
}

// ---------------- fp32 64x64 microkernel (projections) ----------------------
#define MICRO_FMA()                                                            \
    _Pragma("unroll")                                                          \
    for (int kk = 0; kk < 16; kk++) {                                          \
        float4 a = *(const float4*)&Asf[kk][ty * 4];                           \
        float4 b = *(const float4*)&Bsf[kk][tx * 4];                           \
        acc[0][0] += a.x * b.x; acc[0][1] += a.x * b.y;                        \
        acc[0][2] += a.x * b.z; acc[0][3] += a.x * b.w;                        \
        acc[1][0] += a.y * b.x; acc[1][1] += a.y * b.y;                        \
        acc[1][2] += a.y * b.z; acc[1][3] += a.y * b.w;                        \
        acc[2][0] += a.z * b.x; acc[2][1] += a.z * b.y;                        \
        acc[2][2] += a.z * b.z; acc[2][3] += a.z * b.w;                        \
        acc[3][0] += a.w * b.x; acc[3][1] += a.w * b.y;                        \
        acc[3][2] += a.w * b.z; acc[3][3] += a.w * b.w;                        \
    }

// out[m][n] = sum_k X[k][m] * W[n][k] + bias[n]
__global__ void gemm_proj_kernel(const float* __restrict__ X, const float* __restrict__ W,
                                 const float* __restrict__ bias, float* __restrict__ out) {
    __shared__ __align__(16) float Asf[16][68];
    __shared__ __align__(16) float Bsf[16][68];
    int n0 = blockIdx.x * 64, m0 = blockIdx.y * 64;
    int tid = threadIdx.x, tx = tid & 15, ty = tid >> 4;
    int rr = tid >> 2, k4 = tid & 3;
    float acc[4][4] = {};
    for (int kt = 0; kt < 32; kt++) {
        __syncthreads();
#pragma unroll
        for (int r = 0; r < 4; r++) {
            int idx = tid + r * 256;
            int kk = idx >> 6, mmu = idx & 63;
            Asf[kk][mmu] = X[(size_t)(kt * 16 + kk) * S_TOT + m0 + mmu];
        }
        float4 wv = *(const float4*)&W[(size_t)(n0 + rr) * 512 + kt * 16 + k4 * 4];
        Bsf[k4 * 4 + 0][rr] = wv.x;
        Bsf[k4 * 4 + 1][rr] = wv.y;
        Bsf[k4 * 4 + 2][rr] = wv.z;
        Bsf[k4 * 4 + 3][rr] = wv.w;
        __syncthreads();
        MICRO_FMA();
    }
    float4 bvv = *(const float4*)&bias[n0 + tx * 4];
#pragma unroll
    for (int i = 0; i < 4; i++) {
        float4 r;
        r.x = acc[i][0] + bvv.x; r.y = acc[i][1] + bvv.y;
        r.z = acc[i][2] + bvv.z; r.w = acc[i][3] + bvv.w;
        *(float4*)&out[(size_t)(m0 + ty * 4 + i) * 512 + n0 + tx * 4] = r;
    }
}

// out[c][s] = sum_d A[s][d]*Wo[c][d] + bo[c] + resid[c][s]
__global__ void gemm_oproj_kernel(const float* __restrict__ A, const float* __restrict__ W,
                                  const float* __restrict__ bias, const float* __restrict__ resid,
                                  float* __restrict__ out) {
    __shared__ __align__(16) float Asf[16][68];
    __shared__ __align__(16) float Bsf[16][68];
    int n0 = blockIdx.x * 64, m0 = blockIdx.y * 64;
    int tid = threadIdx.x, tx = tid & 15, ty = tid >> 4;
    int rr = tid >> 2, k4 = tid & 3;
    float acc[4][4] = {};
    for (int kt = 0; kt < 32; kt++) {
        __syncthreads();
        float4 av = *(const float4*)&A[(size_t)(m0 + rr) * 512 + kt * 16 + k4 * 4];
        Asf[k4 * 4 + 0][rr] = av.x; Asf[k4 * 4 + 1][rr] = av.y;
        Asf[k4 * 4 + 2][rr] = av.z; Asf[k4 * 4 + 3][rr] = av.w;
        float4 wv = *(const float4*)&W[(size_t)(n0 + rr) * 512 + kt * 16 + k4 * 4];
        Bsf[k4 * 4 + 0][rr] = wv.x; Bsf[k4 * 4 + 1][rr] = wv.y;
        Bsf[k4 * 4 + 2][rr] = wv.z; Bsf[k4 * 4 + 3][rr] = wv.w;
        __syncthreads();
        MICRO_FMA();
    }
#pragma unroll
    for (int j = 0; j < 4; j++) {
        int n = n0 + tx * 4 + j;
        float bn = bias[n];
        float4 rv = *(const float4*)&resid[(size_t)n * S_TOT + m0 + ty * 4];
        float4 r;
        r.x = acc[0][j] + bn + rv.x;
        r.y = acc[1][j] + bn + rv.y;
        r.z = acc[2][j] + bn + rv.z;
        r.w = acc[3][j] + bn + rv.w;
        *(float4*)&out[(size_t)n * S_TOT + m0 + ty * 4] = r;
    }
}

// ---------------- Row softmax over allowed prefix ---------------------------
__global__ void softmax_kernel(float* __restrict__ S) {
    __shared__ float red[256];
    int q = blockIdx.x;
    int L = ((q >> 10) + 1) << 10;
    int n = L >> 8;
    float* row = S + (size_t)q * S_TOT;
    float v[32];
    float mx = -1e30f;
#pragma unroll
    for (int i = 0; i < 32; i++)
        if (i < n) { v[i] = row[i * 256 + threadIdx.x]; mx = fmaxf(mx, v[i]); }
    red[threadIdx.x] = mx;
    __syncthreads();
    for (int off = 128; off > 0; off >>= 1) {
        if (threadIdx.x < off) red[threadIdx.x] = fmaxf(red[threadIdx.x], red[threadIdx.x + off]);
        __syncthreads();
    }
    mx = red[0];
    __syncthreads();
    float s = 0.f;
#pragma unroll
    for (int i = 0; i < 32; i++)
        if (i < n) { v[i] = expf(v[i] - mx); s += v[i]; }
    red[threadIdx.x] = s;
    __syncthreads();
    for (int off = 128; off > 0; off >>= 1) {
        if (threadIdx.x < off) red[threadIdx.x] += red[threadIdx.x + off];
        __syncthreads();
    }
    float inv = 1.f / red[0];
#pragma unroll
    for (int i = 0; i < 32; i++)
        if (i < n) row[i * 256 + threadIdx.x] = v[i] * inv;
}

// ---------------------------- launcher -------------------------------------
extern "C" void kernel_launch(void* const* d_in, const int* in_sizes, int n_in,
                              void* d_out, int out_size) {
    (void)in_sizes; (void)n_in; (void)out_size;
    const float* x      = (const float*)d_in[0];
    const float* r0_n1s = (const float*)d_in[1];
    const float* r0_n1b = (const float*)d_in[2];
    const float* r0_w1  = (const float*)d_in[3];
    const float* r0_b1  = (const float*)d_in[4];
    const float* r0_n2s = (const float*)d_in[5];
    const float* r0_n2b = (const float*)d_in[6];
    const float* r0_w2  = (const float*)d_in[7];
    const float* r0_b2  = (const float*)d_in[8];
    const float* r1_n1s = (const float*)d_in[9];
    const float* r1_n1b = (const float*)d_in[10];
    const float* r1_w1  = (const float*)d_in[11];
    const float* r1_b1  = (const float*)d_in[12];
    const float* r1_n2s = (const float*)d_in[13];
    const float* r1_n2b = (const float*)d_in[14];
    const float* r1_w2  = (const float*)d_in[15];
    const float* r1_b2  = (const float*)d_in[16];
    const float* a_gns  = (const float*)d_in[17];
    const float* a_gnb  = (const float*)d_in[18];
    const float* wq = (const float*)d_in[19];
    const float* bq = (const float*)d_in[20];
    const float* wk = (const float*)d_in[21];
    const float* bk = (const float*)d_in[22];
    const float* wv = (const float*)d_in[23];
    const float* bv = (const float*)d_in[24];
    const float* wo = (const float*)d_in[25];
    const float* bo = (const float*)d_in[26];
    float* out = (float*)d_out;

    float *b0, *b1, *b2, *qb, *kb, *vb, *sc, *padb;
    uint32_t* wfrb;
    cudaGetSymbolAddress((void**)&b0, g_buf0);
    cudaGetSymbolAddress((void**)&b1, g_buf1);
    cudaGetSymbolAddress((void**)&b2, g_buf2);
    cudaGetSymbolAddress((void**)&qb, g_q);
    cudaGetSymbolAddress((void**)&kb, g_k);
    cudaGetSymbolAddress((void**)&vb, g_v);
    cudaGetSymbolAddress((void**)&sc, g_scores);
    cudaGetSymbolAddress((void**)&padb, g_pad);
    cudaGetSymbolAddress((void**)&wfrb, g_wfr);

    const int padblocks = (CCH * PAD_PER_C + 255) / 256;
    const int wfrblocks = (KDIM * CCH / 2) / 256;  // 13824
    dim3 cgrid(64, 4);   // n-tiles (128 spatial), m-tiles (128 co)
    dim3 pgrid(8, 128);  // fp32 proj tiles

#define GN_STATS(ptr) do { \
    gn_part_kernel<<<256, 256>>>(ptr); \
    gn_fin_kernel<<<1, 32>>>(); } while (0)

    offb_kernel<<<(KDIM + 255) / 256, 256>>>();

    // ---- resnet block 0 ----
    GN_STATS(x);
    gn_apply_kernel<<<4096, 256>>>(x, b0, r0_n1s, r0_n1b, 1);
    pad_kernel<<<padblocks, 256>>>(b0, padb);
    wfrag_kernel<<<wfrblocks, 256>>>(r0_w1, wfrb);
    conv_hmma_kernel<<<cgrid, 256>>>(padb, wfrb, r0_b1, nullptr, b1);
    GN_STATS(b1);
    gn_apply_kernel<<<4096, 256>>>(b1, b0, r0_n2s, r0_n2b, 1);
    pad_kernel<<<padblocks, 256>>>(b0, padb);
    wfrag_kernel<<<wfrblocks, 256>>>(r0_w2, wfrb);
    conv_hmma_kernel<<<cgrid, 256>>>(padb, wfrb, r0_b2, x, b2);  // b2 = resnet0 out

    // ---- causal frame attention ----
    GN_STATS(b2);
    gn_apply_kernel<<<4096, 256>>>(b2, b0, a_gns, a_gnb, 0);   // b0 = xn [c][s]
    gemm_proj_kernel<<<pgrid, 256>>>(b0, wq, bq, qb);
    gemm_proj_kernel<<<pgrid, 256>>>(b0, wk, bk, kb);
    gemm_proj_kernel<<<pgrid, 256>>>(b0, wv, bv, vb);
    scores_mma_kernel<<<dim3(64, 64), 256>>>(qb, kb, sc);
    softmax_kernel<<<8192, 256>>>(sc);
    pv_mma_kernel<<<dim3(4, 64), 256>>>(sc, vb, b1);           // b1 = attn O [s][d]
    gemm_oproj_kernel<<<pgrid, 256>>>(b1, wo, bo, b2, b0);     // b0 = attn out [c][s]

    // ---- resnet block 1 ----
    GN_STATS(b0);
    gn_apply_kernel<<<4096, 256>>>(b0, b1, r1_n1s, r1_n1b, 1);
    pad_kernel<<<padblocks, 256>>>(b1, padb);
    wfrag_kernel<<<wfrblocks, 256>>>(r1_w1, wfrb);
    conv_hmma_kernel<<<cgrid, 256>>>(padb, wfrb, r1_b1, nullptr, b2);
    GN_STATS(b2);
    gn_apply_kernel<<<4096, 256>>>(b2, b1, r1_n2s, r1_n2b, 1);
    pad_kernel<<<padblocks, 256>>>(b1, padb);
    wfrag_kernel<<<wfrblocks, 256>>>(r1_w2, wfrb);
    conv_hmma_kernel<<<cgrid, 256>>>(padb, wfrb, r1_b2, b0, out);
}

// round 7
// speedup vs baseline: 6.8345x; 1.0734x over previous
#include <cuda_runtime.h>
#include <cuda_fp16.h>
#include <math.h>
#include <stdint.h>

#define S_TOT 8192           // T*H*W = 8*32*32
#define CCH   512
#define NELEM (CCH * S_TOT)  // 4,194,304
#define PAD_PER_C 11560      // 10*34*34
#define KDIM 13824           // 512*27
#define KT32 432             // KDIM/32

// ---------------- scratch (device globals: allocation-free) ----------------
__device__ float g_buf0[NELEM];
__device__ float g_buf1[NELEM];
__device__ float g_buf2[NELEM];
__device__ float g_q[NELEM];
__device__ float g_k[NELEM];
__device__ float g_v[NELEM];
__device__ float g_scores[(size_t)S_TOT * S_TOT];  // 256 MB
__device__ float g_pad[CCH * PAD_PER_C];           // padded conv input
__device__ uint32_t g_wfr[KDIM * CCH / 2];         // fp16 fragment-packed weights
__device__ int   g_offB[KDIM];                     // per-k pad offset table
__device__ float2 g_part[256];
__device__ float g_mean[32];
__device__ float g_rstd[32];

// ---------------- MMA primitives -------------------------------------------
__device__ __forceinline__ void mma_tf32(float c[4], uint32_t a0, uint32_t a1,
                                         uint32_t a2, uint32_t a3,
                                         uint32_t b0, uint32_t b1) {
    asm volatile(
        "mma.sync.aligned.m16n8k8.row.col.f32.tf32.tf32.f32 "
        "{%0,%1,%2,%3}, {%4,%5,%6,%7}, {%8,%9}, {%0,%1,%2,%3};\n"
        : "+f"(c[0]), "+f"(c[1]), "+f"(c[2]), "+f"(c[3])
        : "r"(a0), "r"(a1), "r"(a2), "r"(a3), "r"(b0), "r"(b1));
}
__device__ __forceinline__ void mma_f16(float c[4], uint32_t a0, uint32_t a1,
                                        uint32_t a2, uint32_t a3,
                                        uint32_t b0, uint32_t b1) {
    asm volatile(
        "mma.sync.aligned.m16n8k16.row.col.f32.f16.f16.f32 "
        "{%0,%1,%2,%3}, {%4,%5,%6,%7}, {%8,%9}, {%0,%1,%2,%3};\n"
        : "+f"(c[0]), "+f"(c[1]), "+f"(c[2]), "+f"(c[3])
        : "r"(a0), "r"(a1), "r"(a2), "r"(a3), "r"(b0), "r"(b1));
}
__device__ __forceinline__ uint32_t f2tf32(float x) {
    uint32_t r;
    asm("cvt.rna.tf32.f32 %0, %1;" : "=r"(r) : "f"(x));
    return r;
}
__device__ __forceinline__ uint32_t f2h2(float lo, float hi) {
    __half2 h = __floats2half2_rn(lo, hi);
    return *(uint32_t*)&h;
}

// legacy (matrix-order smem) tf32 warp-tile compute for scores/pv kernels
#define MMA_COMPUTE(buf)                                                     \
    _Pragma("unroll")                                                        \
    for (int ks = 0; ks < 2; ks++) {                                         \
        uint32_t af[4][4], bf[4][2];                                         \
        _Pragma("unroll")                                                    \
        for (int i2 = 0; i2 < 4; i2++) {                                     \
            af[i2][0] = As[buf][ks * 8 + tig][mw + i2 * 16 + grp];           \
            af[i2][1] = As[buf][ks * 8 + tig][mw + i2 * 16 + grp + 8];       \
            af[i2][2] = As[buf][ks * 8 + tig + 4][mw + i2 * 16 + grp];       \
            af[i2][3] = As[buf][ks * 8 + tig + 4][mw + i2 * 16 + grp + 8];   \
        }                                                                    \
        _Pragma("unroll")                                                    \
        for (int j2 = 0; j2 < 4; j2++) {                                     \
            bf[j2][0] = Bs[buf][ks * 8 + tig][nw + j2 * 8 + grp];            \
            bf[j2][1] = Bs[buf][ks * 8 + tig + 4][nw + j2 * 8 + grp];        \
        }                                                                    \
        _Pragma("unroll")                                                    \
        for (int i2 = 0; i2 < 4; i2++)                                       \
            _Pragma("unroll")                                                \
            for (int j2 = 0; j2 < 4; j2++)                                   \
                mma_tf32(c[i2][j2], af[i2][0], af[i2][1], af[i2][2],         \
                         af[i2][3], bf[j2][0], bf[j2][1]);                   \
    }

// ---------------- GroupNorm stats: partial + finalize -----------------------
__global__ void gn_part_kernel(const float* __restrict__ x) {
    __shared__ float rs[256], rq[256];
    int g = blockIdx.x >> 3, ch = blockIdx.x & 7;
    const float* base = x + (size_t)g * 16 * S_TOT + ch * 16384;
    float s = 0.f, ss = 0.f;
    for (int i = threadIdx.x; i < 16384; i += 256) {
        float v = base[i];
        s += v;
        ss += v * v;
    }
    rs[threadIdx.x] = s;
    rq[threadIdx.x] = ss;
    __syncthreads();
    for (int off = 128; off > 0; off >>= 1) {
        if (threadIdx.x < off) {
            rs[threadIdx.x] += rs[threadIdx.x + off];
            rq[threadIdx.x] += rq[threadIdx.x + off];
        }
        __syncthreads();
    }
    if (threadIdx.x == 0) g_part[blockIdx.x] = make_float2(rs[0], rq[0]);
}

__global__ void gn_fin_kernel() {
    int g = threadIdx.x;
    if (g < 32) {
        float s = 0.f, ss = 0.f;
        for (int c = 0; c < 8; c++) {
            float2 p = g_part[g * 8 + c];
            s += p.x;
            ss += p.y;
        }
        float mean = s * (1.f / 131072.f);
        float var = ss * (1.f / 131072.f) - mean * mean;
        g_mean[g] = mean;
        g_rstd[g] = rsqrtf(var + 1e-6f);
    }
}

// ---------------- GroupNorm apply (+SiLU) ----------------------------------
__global__ void gn_apply_kernel(const float* __restrict__ x, float* __restrict__ y,
                                const float* __restrict__ sc, const float* __restrict__ bi,
                                int do_silu) {
    int i4 = blockIdx.x * blockDim.x + threadIdx.x;
    int c = i4 >> 11;
    int g = c >> 4;
    float rstd = g_rstd[g];
    float a = sc[c] * rstd;
    float b = bi[c] - g_mean[g] * a;
    float4 v = ((const float4*)x)[i4];
    float4 r;
    r.x = a * v.x + b;
    r.y = a * v.y + b;
    r.z = a * v.z + b;
    r.w = a * v.w + b;
    if (do_silu) {
        r.x = r.x / (1.f + expf(-r.x));
        r.y = r.y / (1.f + expf(-r.y));
        r.z = r.z / (1.f + expf(-r.z));
        r.w = r.w / (1.f + expf(-r.w));
    }
    ((float4*)y)[i4] = r;
}

// ---------------- conv input pre-pad (replicate; causal t) ------------------
__global__ void pad_kernel(const float* __restrict__ in, float* __restrict__ pad) {
    int idx = blockIdx.x * 256 + threadIdx.x;
    if (idx >= CCH * PAD_PER_C) return;
    int ci = idx / PAD_PER_C, r = idx - ci * PAD_PER_C;
    int tp = r / 1156, r2 = r - tp * 1156;
    int hp = r2 / 34, wp = r2 - hp * 34;
    int t = tp - 2; t = t < 0 ? 0 : t;
    int h = hp - 1; h = h < 0 ? 0 : (h > 31 ? 31 : h);
    int w = wp - 1; w = w < 0 ? 0 : (w > 31 ? 31 : w);
    pad[idx] = in[(size_t)ci * S_TOT + t * 1024 + h * 32 + w];
}

// ---------------- per-k offset table for the conv B gather ------------------
__global__ void offb_kernel() {
    int k = blockIdx.x * 256 + threadIdx.x;
    if (k >= KDIM) return;
    int ci = k / 27, tap = k - ci * 27;
    int kd = tap / 9, r2 = tap - kd * 9;
    int kh = r2 / 3, kw = r2 - kh * 3;
    g_offB[k] = ci * PAD_PER_C + kd * 1156 + kh * 34 + kw;
}

// ---------------- weight fragment pack: w[co][k] -> fp16 A-fragment images --
__global__ void wfrag_kernel(const float* __restrict__ w, uint32_t* __restrict__ dst) {
    int idx = blockIdx.x * 256 + threadIdx.x;
    if (idx >= KDIM * CCH / 2) return;
    int reg = idx & 3, lane = (idx >> 2) & 31;
    int r2 = idx >> 7;
    int mtile = r2 & 7, ks = (r2 >> 3) & 1;
    int ktm = r2 >> 4;
    int kt = ktm % KT32, mt = ktm / KT32;
    int m = mt * 128 + mtile * 16 + (reg & 1) * 8 + (lane >> 2);
    int k = kt * 32 + ks * 16 + (reg >> 1) * 8 + 2 * (lane & 3);
    const float* src = &w[(size_t)m * KDIM + k];
    dst[idx] = f2h2(src[0], src[1]);
}

// ---------------- Conv3d implicit GEMM, fp16 m16n8k16 -----------------------
__global__ void __launch_bounds__(256, 2)
conv_hmma_kernel(const float* __restrict__ pad, const uint32_t* __restrict__ wfr,
                 const float* __restrict__ bias, const float* __restrict__ resid,
                 float* __restrict__ out) {
    __shared__ __align__(16) uint32_t Asm[2][2048];
    __shared__ __align__(16) uint32_t Bsm[2][2112];
    const int tid = threadIdx.x, lane = tid & 31, wid = tid >> 5;
    const int tig = lane & 3, grp = lane >> 2;
    const int mt0 = (wid >> 2) * 4, nt0 = (wid & 3) * 4;
    const int mw = (wid >> 2) * 64, nw = (wid & 3) * 32;
    const int n0 = blockIdx.x * 128, m0 = blockIdx.y * 128;
    const int mt = blockIdx.y;
    const int t = n0 >> 10, h0 = (n0 >> 5) & 31;
    const int kp = tid >> 5;

    int sb[4];
#pragma unroll
    for (int r = 0; r < 4; r++) sb[r] = t * 1156 + (h0 + r) * 34 + lane;
    int boff[4];
#pragma unroll
    for (int r = 0; r < 4; r++) {
        int ntile = r * 4 + (lane >> 3), nin = lane & 7;
        boff[r] = ntile * 66 + (nin * 4 + (kp & 3)) * 2 + (kp >> 2);
    }

    float c[4][4][4];
#pragma unroll
    for (int i = 0; i < 4; i++)
#pragma unroll
        for (int j = 0; j < 4; j++)
#pragma unroll
            for (int q = 0; q < 4; q++) c[i][j][q] = 0.f;

    uint4 areg0, areg1;
    float brg[4][4];

#define CV_LDG(kt) {                                                         \
    const uint4* asrc = (const uint4*)wfr + (size_t)(mt * KT32 + (kt)) * 512;\
    areg0 = asrc[tid];                                                       \
    areg1 = asrc[tid + 256];                                                 \
    int kb = (kt) * 32 + 2 * kp;                                             \
    int o00 = g_offB[kb], o01 = g_offB[kb + 1];                              \
    int o10 = g_offB[kb + 16], o11 = g_offB[kb + 17];                        \
    _Pragma("unroll")                                                        \
    for (int r = 0; r < 4; r++) {                                            \
        brg[r][0] = pad[o00 + sb[r]];                                        \
        brg[r][1] = pad[o01 + sb[r]];                                        \
        brg[r][2] = pad[o10 + sb[r]];                                        \
        brg[r][3] = pad[o11 + sb[r]];                                        \
    } }

#define CV_STS(buf) {                                                        \
    ((uint4*)&Asm[buf][0])[tid] = areg0;                                     \
    ((uint4*)&Asm[buf][0])[tid + 256] = areg1;                               \
    _Pragma("unroll")                                                        \
    for (int r = 0; r < 4; r++) {                                            \
        Bsm[buf][boff[r]] = f2h2(brg[r][0], brg[r][1]);                      \
        Bsm[buf][boff[r] + 16 * 66] = f2h2(brg[r][2], brg[r][3]);            \
    } }

#define CV_MMA(buf)                                                          \
    _Pragma("unroll")                                                        \
    for (int ks = 0; ks < 2; ks++) {                                         \
        uint4 av[4];                                                         \
        uint2 bv2[4];                                                        \
        _Pragma("unroll")                                                    \
        for (int i2 = 0; i2 < 4; i2++)                                       \
            av[i2] = *(const uint4*)&Asm[buf][(ks * 8 + mt0 + i2) * 128 + lane * 4]; \
        _Pragma("unroll")                                                    \
        for (int j2 = 0; j2 < 4; j2++)                                       \
            bv2[j2] = *(const uint2*)&Bsm[buf][(ks * 16 + nt0 + j2) * 66 + lane * 2]; \
        _Pragma("unroll")                                                    \
        for (int i2 = 0; i2 < 4; i2++)                                       \
            _Pragma("unroll")                                                \
            for (int j2 = 0; j2 < 4; j2++)                                   \
                mma_f16(c[i2][j2], av[i2].x, av[i2].y, av[i2].z, av[i2].w,   \
                        bv2[j2].x, bv2[j2].y);                               \
    }

    CV_LDG(0);
    CV_STS(0);
    __syncthreads();
#pragma unroll 1
    for (int kt = 0; kt < KT32; kt++) {
        int cur = kt & 1;
        if (kt + 1 < KT32) CV_LDG(kt + 1);
        CV_MMA(cur);
        if (kt + 1 < KT32) CV_STS(cur ^ 1);
        __syncthreads();
    }

#pragma unroll
    for (int i = 0; i < 4; i++)
#pragma unroll
        for (int half = 0; half < 2; half++) {
            int co = m0 + mw + i * 16 + grp + half * 8;
            float bv = bias[co];
            size_t rowbase = (size_t)co * S_TOT + n0;
#pragma unroll
            for (int j = 0; j < 4; j++) {
                int col = nw + j * 8 + 2 * tig;
                float2 v;
                v.x = c[i][j][half * 2 + 0] + bv;
                v.y = c[i][j][half * 2 + 1] + bv;
                if (resid) {
                    v.x += resid[rowbase + col];
                    v.y += resid[rowbase + col + 1];
                }
                *(float2*)&out[rowbase + col] = v;
            }
        }
}

// ---------------- fp16 HMMA projection GEMM ---------------------------------
// m = s (8192, from X[k][s] k-major), n = c (512, from W[c][k]), K = 512.
// MODE 0: out[s][c] = sum + bias          (Q/K/V projections)
// MODE 1: out[c][s] = sum + bias + resid  (o-projection; X = O in [d][s])
template <int MODE>
__global__ void __launch_bounds__(256, 2)
proj_hmma_kernel(const float* __restrict__ X, const float* __restrict__ W,
                 const float* __restrict__ bias, const float* __restrict__ resid,
                 float* __restrict__ out) {
    __shared__ __align__(16) uint32_t Asm[2][2112];  // 16 tiles * 132 stride
    __shared__ __align__(16) uint32_t Bsm[2][2112];
    const int tid = threadIdx.x, lane = tid & 31, wid = tid >> 5;
    const int tig = lane & 3, grp = lane >> 2;
    const int mt0 = (wid >> 2) * 4, nt0 = (wid & 3) * 4;
    const int mw = (wid >> 2) * 64, nw = (wid & 3) * 32;
    const int n0 = blockIdx.x * 128, m0 = blockIdx.y * 128;
    const int kp = tid >> 5;

    // A producer STS offsets: padded fragment layout, stride 132 per tile
    int aoff[4][2];
#pragma unroll
    for (int r = 0; r < 4; r++) {
        int m = r * 32 + lane;
        int lane_c = (m & 7) * 4 + (kp & 3);
        int reg0 = (kp >> 2) * 2 + ((m >> 3) & 1);
#pragma unroll
        for (int ks = 0; ks < 2; ks++)
            aoff[r][ks] = (ks * 8 + (m >> 4)) * 132 + lane_c * 4 + reg0;
    }
    int boff[4];
#pragma unroll
    for (int r = 0; r < 4; r++) {
        int cc = r * 32 + lane;
        boff[r] = (cc >> 3) * 66 + (cc & 7) * 8 + (kp & 3) * 2 + (kp >> 2);
    }

    float c[4][4][4];
#pragma unroll
    for (int i = 0; i < 4; i++)
#pragma unroll
        for (int j = 0; j < 4; j++)
#pragma unroll
            for (int q = 0; q < 4; q++) c[i][j][q] = 0.f;

    float arg[4][2][2];   // [r][ks][pair-half]
    float2 wrg[4][2];     // [r][ks]

#define PR_LDG(kt) {                                                         \
    int kb = (kt) * 32;                                                      \
    _Pragma("unroll")                                                        \
    for (int ks = 0; ks < 2; ks++) {                                         \
        const float* x0 = &X[(size_t)(kb + ks * 16 + 2 * kp) * S_TOT + m0 + lane]; \
        _Pragma("unroll")                                                    \
        for (int r = 0; r < 4; r++) {                                        \
            arg[r][ks][0] = x0[r * 32];                                      \
            arg[r][ks][1] = x0[S_TOT + r * 32];                              \
        }                                                                    \
    }                                                                        \
    _Pragma("unroll")                                                        \
    for (int r = 0; r < 4; r++) {                                            \
        const float* wp2 = &W[(size_t)(n0 + r * 32 + lane) * 512 + kb + 2 * kp]; \
        wrg[r][0] = *(const float2*)wp2;                                     \
        wrg[r][1] = *(const float2*)(wp2 + 16);                              \
    } }

#define PR_STS(buf) {                                                        \
    _Pragma("unroll")                                                        \
    for (int r = 0; r < 4; r++) {                                            \
        Asm[buf][aoff[r][0]] = f2h2(arg[r][0][0], arg[r][0][1]);             \
        Asm[buf][aoff[r][1]] = f2h2(arg[r][1][0], arg[r][1][1]);             \
        Bsm[buf][boff[r]] = f2h2(wrg[r][0].x, wrg[r][0].y);                  \
        Bsm[buf][boff[r] + 16 * 66] = f2h2(wrg[r][1].x, wrg[r][1].y);        \
    } }

#define PR_MMA(buf)                                                          \
    _Pragma("unroll")                                                        \
    for (int ks = 0; ks < 2; ks++) {                                         \
        uint4 av[4];                                                         \
        uint2 bv2[4];                                                        \
        _Pragma("unroll")                                                    \
        for (int i2 = 0; i2 < 4; i2++)                                       \
            av[i2] = *(const uint4*)&Asm[buf][(ks * 8 + mt0 + i2) * 132 + lane * 4]; \
        _Pragma("unroll")                                                    \
        for (int j2 = 0; j2 < 4; j2++)                                       \
            bv2[j2] = *(const uint2*)&Bsm[buf][(ks * 16 + nt0 + j2) * 66 + lane * 2]; \
        _Pragma("unroll")                                                    \
        for (int i2 = 0; i2 < 4; i2++)                                       \
            _Pragma("unroll")                                                \
            for (int j2 = 0; j2 < 4; j2++)                                   \
                mma_f16(c[i2][j2], av[i2].x, av[i2].y, av[i2].z, av[i2].w,   \
                        bv2[j2].x, bv2[j2].y);                               \
    }

    PR_LDG(0);
    PR_STS(0);
    __syncthreads();
#pragma unroll 1
    for (int kt = 0; kt < 16; kt++) {
        int cur = kt & 1;
        if (kt + 1 < 16) PR_LDG(kt + 1);
        PR_MMA(cur);
        if (kt + 1 < 16) PR_STS(cur ^ 1);
        __syncthreads();
    }

#pragma unroll
    for (int i = 0; i < 4; i++)
#pragma unroll
        for (int half = 0; half < 2; half++) {
            int srow = m0 + mw + i * 16 + grp + half * 8;
#pragma unroll
            for (int j = 0; j < 4; j++) {
                int ccol = n0 + nw + j * 8 + 2 * tig;
                float v0 = c[i][j][half * 2 + 0];
                float v1 = c[i][j][half * 2 + 1];
                if (MODE == 0) {
                    float2 bv = *(const float2*)&bias[ccol];
                    float2 o;
                    o.x = v0 + bv.x;
                    o.y = v1 + bv.y;
                    *(float2*)&out[(size_t)srow * 512 + ccol] = o;
                } else {
                    size_t i0 = (size_t)ccol * S_TOT + srow;
                    size_t i1 = (size_t)(ccol + 1) * S_TOT + srow;
                    out[i0] = v0 + bias[ccol] + resid[i0];
                    out[i1] = v1 + bias[ccol + 1] + resid[i1];
                }
            }
        }
}

// ---------------- Scores: S = scale * Q K^T (tf32, frame-causal skip) -------
__global__ void __launch_bounds__(256, 2)
scores_mma_kernel(const float* __restrict__ Q, const float* __restrict__ Kd,
                  float* __restrict__ S) {
    const int n0 = blockIdx.x * 128, m0 = blockIdx.y * 128;
    if ((n0 >> 10) > (m0 >> 10)) return;
    __shared__ uint32_t As[2][16][136];
    __shared__ uint32_t Bs[2][16][136];
    const int tid = threadIdx.x, lane = tid & 31, wid = tid >> 5;
    const int tig = lane & 3, grp = lane >> 2;
    const int mw = (wid >> 2) * 64, nw = (wid & 3) * 32;
    const int mm = tid >> 1, kk0 = (tid & 1) * 8;

    float c[4][4][4];
#pragma unroll
    for (int i = 0; i < 4; i++)
#pragma unroll
        for (int j = 0; j < 4; j++)
#pragma unroll
            for (int q = 0; q < 4; q++) c[i][j][q] = 0.f;

    float4 aq0, aq1, bq0, bq1;

#define SC_LDG(kt) {                                                         \
    int kb = (kt) * 16;                                                      \
    const float* qp = &Q[(size_t)(m0 + mm) * 512 + kb + kk0];                \
    aq0 = *(const float4*)qp; aq1 = *(const float4*)(qp + 4);                \
    const float* kp2 = &Kd[(size_t)(n0 + mm) * 512 + kb + kk0];              \
    bq0 = *(const float4*)kp2; bq1 = *(const float4*)(kp2 + 4); }

#define SC_STS(buf) {                                                        \
    As[buf][kk0 + 0][mm] = f2tf32(aq0.x);                                    \
    As[buf][kk0 + 1][mm] = f2tf32(aq0.y);                                    \
    As[buf][kk0 + 2][mm] = f2tf32(aq0.z);                                    \
    As[buf][kk0 + 3][mm] = f2tf32(aq0.w);                                    \
    As[buf][kk0 + 4][mm] = f2tf32(aq1.x);                                    \
    As[buf][kk0 + 5][mm] = f2tf32(aq1.y);                                    \
    As[buf][kk0 + 6][mm] = f2tf32(aq1.z);                                    \
    As[buf][kk0 + 7][mm] = f2tf32(aq1.w);                                    \
    Bs[buf][kk0 + 0][mm] = f2tf32(bq0.x);                                    \
    Bs[buf][kk0 + 1][mm] = f2tf32(bq0.y);                                    \
    Bs[buf][kk0 + 2][mm] = f2tf32(bq0.z);                                    \
    Bs[buf][kk0 + 3][mm] = f2tf32(bq0.w);                                    \
    Bs[buf][kk0 + 4][mm] = f2tf32(bq1.x);                                    \
    Bs[buf][kk0 + 5][mm] = f2tf32(bq1.y);                                    \
    Bs[buf][kk0 + 6][mm] = f2tf32(bq1.z);                                    \
    Bs[buf][kk0 + 7][mm] = f2tf32(bq1.w); }

    SC_LDG(0);
    SC_STS(0);
    __syncthreads();
    const int KT = 32;
#pragma unroll 1
    for (int kt = 0; kt < KT; kt++) {
        int cur = kt & 1;
        if (kt + 1 < KT) SC_LDG(kt + 1);
        MMA_COMPUTE(cur);
        if (kt + 1 < KT) SC_STS(cur ^ 1);
        __syncthreads();
    }

    const float scale = 0.04419417382415922f;  // 512^-0.5
#pragma unroll
    for (int i = 0; i < 4; i++)
#pragma unroll
        for (int half = 0; half < 2; half++) {
            int row = mw + i * 16 + grp + half * 8;
            size_t rowbase = (size_t)(m0 + row) * S_TOT + n0;
#pragma unroll
            for (int j = 0; j < 4; j++) {
                int col = nw + j * 8 + 2 * tig;
                float2 v;
                v.x = c[i][j][half * 2 + 0] * scale;
                v.y = c[i][j][half * 2 + 1] * scale;
                *(float2*)&S[rowbase + col] = v;
            }
        }
}

// ---------------- PV: O = P(prefix) * V (tf32), output [d][s] ---------------
__global__ void __launch_bounds__(256, 2)
pv_mma_kernel(const float* __restrict__ P, const float* __restrict__ V,
              float* __restrict__ out) {
    const int n0 = blockIdx.x * 128, m0 = blockIdx.y * 128;
    __shared__ uint32_t As[2][16][136];
    __shared__ uint32_t Bs[2][16][136];
    const int tid = threadIdx.x, lane = tid & 31, wid = tid >> 5;
    const int tig = lane & 3, grp = lane >> 2;
    const int mw = (wid >> 2) * 64, nw = (wid & 3) * 32;
    const int mm = tid >> 1, kk0 = (tid & 1) * 8;
    const int vrow = tid >> 4, vcol = (tid & 15) * 8;

    float c[4][4][4];
#pragma unroll
    for (int i = 0; i < 4; i++)
#pragma unroll
        for (int j = 0; j < 4; j++)
#pragma unroll
            for (int q = 0; q < 4; q++) c[i][j][q] = 0.f;

    float4 ap0, ap1, bv0, bv1;

#define PV_LDG(kt) {                                                         \
    int kb = (kt) * 16;                                                      \
    const float* pp = &P[(size_t)(m0 + mm) * S_TOT + kb + kk0];              \
    ap0 = *(const float4*)pp; ap1 = *(const float4*)(pp + 4);                \
    const float* vp = &V[(size_t)(kb + vrow) * 512 + n0 + vcol];             \
    bv0 = *(const float4*)vp; bv1 = *(const float4*)(vp + 4); }

#define PV_STS(buf) {                                                        \
    As[buf][kk0 + 0][mm] = f2tf32(ap0.x);                                    \
    As[buf][kk0 + 1][mm] = f2tf32(ap0.y);                                    \
    As[buf][kk0 + 2][mm] = f2tf32(ap0.z);                                    \
    As[buf][kk0 + 3][mm] = f2tf32(ap0.w);                                    \
    As[buf][kk0 + 4][mm] = f2tf32(ap1.x);                                    \
    As[buf][kk0 + 5][mm] = f2tf32(ap1.y);                                    \
    As[buf][kk0 + 6][mm] = f2tf32(ap1.z);                                    \
    As[buf][kk0 + 7][mm] = f2tf32(ap1.w);                                    \
    uint4 s0, s1;                                                            \
    s0.x = f2tf32(bv0.x); s0.y = f2tf32(bv0.y);                              \
    s0.z = f2tf32(bv0.z); s0.w = f2tf32(bv0.w);                              \
    s1.x = f2tf32(bv1.x); s1.y = f2tf32(bv1.y);                              \
    s1.z = f2tf32(bv1.z); s1.w = f2tf32(bv1.w);                              \
    *(uint4*)&Bs[buf][vrow][vcol] = s0;                                      \
    *(uint4*)&Bs[buf][vrow][vcol + 4] = s1; }

    PV_LDG(0);
    PV_STS(0);
    __syncthreads();
    const int KT = ((m0 >> 10) + 1) * 64;  // allowed prefix / 16
#pragma unroll 1
    for (int kt = 0; kt < KT; kt++) {
        int cur = kt & 1;
        if (kt + 1 < KT) PV_LDG(kt + 1);
        MMA_COMPUTE(cur);
        if (kt + 1 < KT) PV_STS(cur ^ 1);
        __syncthreads();
    }

    // write transposed: out[d][s]  (feeds MODE-1 proj as its k-major A)
#pragma unroll
    for (int i = 0; i < 4; i++)
#pragma unroll
        for (int half = 0; half < 2; half++) {
            int row = m0 + mw + i * 16 + grp + half * 8;  // q (s)
#pragma unroll
            for (int j = 0; j < 4; j++) {
                int col = n0 + nw + j * 8 + 2 * tig;      // d
                out[(size_t)col * S_TOT + row] = c[i][j][half * 2 + 0];
                out[(size_t)(col + 1) * S_TOT + row] = c[i][j][half * 2 + 1];
            }
        }
}

// ---------------- Row softmax over allowed prefix ---------------------------
__global__ void softmax_kernel(float* __restrict__ S) {
    __shared__ float red[256];
    int q = blockIdx.x;
    int L = ((q >> 10) + 1) << 10;
    int n = L >> 8;
    float* row = S + (size_t)q * S_TOT;
    float v[32];
    float mx = -1e30f;
#pragma unroll
    for (int i = 0; i < 32; i++)
        if (i < n) { v[i] = row[i * 256 + threadIdx.x]; mx = fmaxf(mx, v[i]); }
    red[threadIdx.x] = mx;
    __syncthreads();
    for (int off = 128; off > 0; off >>= 1) {
        if (threadIdx.x < off) red[threadIdx.x] = fmaxf(red[threadIdx.x], red[threadIdx.x + off]);
        __syncthreads();
    }
    mx = red[0];
    __syncthreads();
    float s = 0.f;
#pragma unroll
    for (int i = 0; i < 32; i++)
        if (i < n) { v[i] = expf(v[i] - mx); s += v[i]; }
    red[threadIdx.x] = s;
    __syncthreads();
    for (int off = 128; off > 0; off >>= 1) {
        if (threadIdx.x < off) red[threadIdx.x] += red[threadIdx.x + off];
        __syncthreads();
    }
    float inv = 1.f / red[0];
#pragma unroll
    for (int i = 0; i < 32; i++)
        if (i < n) row[i * 256 + threadIdx.x] = v[i] * inv;
}

// ---------------------------- launcher -------------------------------------
extern "C" void kernel_launch(void* const* d_in, const int* in_sizes, int n_in,
                              void* d_out, int out_size) {
    (void)in_sizes; (void)n_in; (void)out_size;
    const float* x      = (const float*)d_in[0];
    const float* r0_n1s = (const float*)d_in[1];
    const float* r0_n1b = (const float*)d_in[2];
    const float* r0_w1  = (const float*)d_in[3];
    const float* r0_b1  = (const float*)d_in[4];
    const float* r0_n2s = (const float*)d_in[5];
    const float* r0_n2b = (const float*)d_in[6];
    const float* r0_w2  = (const float*)d_in[7];
    const float* r0_b2  = (const float*)d_in[8];
    const float* r1_n1s = (const float*)d_in[9];
    const float* r1_n1b = (const float*)d_in[10];
    const float* r1_w1  = (const float*)d_in[11];
    const float* r1_b1  = (const float*)d_in[12];
    const float* r1_n2s = (const float*)d_in[13];
    const float* r1_n2b = (const float*)d_in[14];
    const float* r1_w2  = (const float*)d_in[15];
    const float* r1_b2  = (const float*)d_in[16];
    const float* a_gns  = (const float*)d_in[17];
    const float* a_gnb  = (const float*)d_in[18];
    const float* wq = (const float*)d_in[19];
    const float* bq = (const float*)d_in[20];
    const float* wk = (const float*)d_in[21];
    const float* bk = (const float*)d_in[22];
    const float* wv = (const float*)d_in[23];
    const float* bv = (const float*)d_in[24];
    const float* wo = (const float*)d_in[25];
    const float* bo = (const float*)d_in[26];
    float* out = (float*)d_out;

    float *b0, *b1, *b2, *qb, *kb, *vb, *sc, *padb;
    uint32_t* wfrb;
    cudaGetSymbolAddress((void**)&b0, g_buf0);
    cudaGetSymbolAddress((void**)&b1, g_buf1);
    cudaGetSymbolAddress((void**)&b2, g_buf2);
    cudaGetSymbolAddress((void**)&qb, g_q);
    cudaGetSymbolAddress((void**)&kb, g_k);
    cudaGetSymbolAddress((void**)&vb, g_v);
    cudaGetSymbolAddress((void**)&sc, g_scores);
    cudaGetSymbolAddress((void**)&padb, g_pad);
    cudaGetSymbolAddress((void**)&wfrb, g_wfr);

    const int padblocks = (CCH * PAD_PER_C + 255) / 256;
    const int wfrblocks = (KDIM * CCH / 2) / 256;  // 13824
    dim3 cgrid(64, 4);    // conv: n-tiles (128 spatial), m-tiles (128 co)
    dim3 prgrid(4, 64);   // proj: n-tiles (128 ch), m-tiles (128 s)

#define GN_STATS(ptr) do { \
    gn_part_kernel<<<256, 256>>>(ptr); \
    gn_fin_kernel<<<1, 32>>>(); } while (0)

    offb_kernel<<<(KDIM + 255) / 256, 256>>>();

    // ---- resnet block 0 ----
    GN_STATS(x);
    gn_apply_kernel<<<4096, 256>>>(x, b0, r0_n1s, r0_n1b, 1);
    pad_kernel<<<padblocks, 256>>>(b0, padb);
    wfrag_kernel<<<wfrblocks, 256>>>(r0_w1, wfrb);
    conv_hmma_kernel<<<cgrid, 256>>>(padb, wfrb, r0_b1, nullptr, b1);
    GN_STATS(b1);
    gn_apply_kernel<<<4096, 256>>>(b1, b0, r0_n2s, r0_n2b, 1);
    pad_kernel<<<padblocks, 256>>>(b0, padb);
    wfrag_kernel<<<wfrblocks, 256>>>(r0_w2, wfrb);
    conv_hmma_kernel<<<cgrid, 256>>>(padb, wfrb, r0_b2, x, b2);  // b2 = resnet0 out

    // ---- causal frame attention ----
    GN_STATS(b2);
    gn_apply_kernel<<<4096, 256>>>(b2, b0, a_gns, a_gnb, 0);   // b0 = xn [c][s]
    proj_hmma_kernel<0><<<prgrid, 256>>>(b0, wq, bq, nullptr, qb);
    proj_hmma_kernel<0><<<prgrid, 256>>>(b0, wk, bk, nullptr, kb);
    proj_hmma_kernel<0><<<prgrid, 256>>>(b0, wv, bv, nullptr, vb);
    scores_mma_kernel<<<dim3(64, 64), 256>>>(qb, kb, sc);
    softmax_kernel<<<8192, 256>>>(sc);
    pv_mma_kernel<<<dim3(4, 64), 256>>>(sc, vb, b1);           // b1 = attn O [d][s]
    proj_hmma_kernel<1><<<prgrid, 256>>>(b1, wo, bo, b2, b0);  // b0 = attn out [c][s]

    // ---- resnet block 1 ----
    GN_STATS(b0);
    gn_apply_kernel<<<4096, 256>>>(b0, b1, r1_n1s, r1_n1b, 1);
    pad_kernel<<<padblocks, 256>>>(b1, padb);
    wfrag_kernel<<<wfrblocks, 256>>>(r1_w1, wfrb);
    conv_hmma_kernel<<<cgrid, 256>>>(padb, wfrb, r1_b1, nullptr, b2);
    GN_STATS(b2);
    gn_apply_kernel<<<4096, 256>>>(b2, b1, r1_n2s, r1_n2b, 1);
    pad_kernel<<<padblocks, 256>>>(b1, padb);
    wfrag_kernel<<<wfrblocks, 256>>>(r1_w2, wfrb);
    conv_hmma_kernel<<<cgrid, 256>>>(padb, wfrb, r1_b2, b0, out);
}